// round 1
// baseline (speedup 1.0000x reference)
#include <cuda_runtime.h>

#define NG 2048
static const int NMAX = 100000;

// Scratch (device globals — no allocations allowed)
__device__ __align__(16) float g_bufA[NMAX * 64];
__device__ __align__(16) float g_bufB[NMAX * 64];
__device__ float g_dinv[NMAX];
__device__ float g_cnt[2 * NG];

// ---------------------------------------------------------------------------
__global__ void k_fill(float* p, float v, int n) {
    int i = blockIdx.x * blockDim.x + threadIdx.x;
    if (i < n) p[i] = v;
}

__global__ void k_deg(const int* __restrict__ dst, int E, float* deg) {
    int stride = gridDim.x * blockDim.x;
    for (int i = blockIdx.x * blockDim.x + threadIdx.x; i < E; i += stride)
        atomicAdd(&deg[dst[i]], 1.0f);
}

__global__ void k_rsqrt(float* p, int n) {
    int i = blockIdx.x * blockDim.x + threadIdx.x;
    if (i < n) p[i] = rsqrtf(p[i]);
}

// ---------------------------------------------------------------------------
// h = act(x) @ W   (W row-major [FIN, FOUT])
// Block: 256 threads. Each thread computes 4 rows x 4 cols.
template <int FIN, int FOUT, bool RELU>
__global__ void k_gemm(const float* __restrict__ x, const float* __restrict__ W,
                       float* __restrict__ h, int N) {
    constexpr int CQ = FOUT / 4;          // column quads
    constexpr int RQ = 256 / CQ;          // row groups of threads
    constexpr int RPB = RQ * 4;           // rows per block iteration
    __shared__ float Ws[FIN * FOUT];
    __shared__ float xs[RPB * FIN];
    int tid = threadIdx.x;
    for (int i = tid; i < FIN * FOUT; i += 256) Ws[i] = W[i];
    int cq = tid % CQ;
    int rg = tid / CQ;
    int r0 = rg * 4;
    for (int base = blockIdx.x * RPB; base < N; base += gridDim.x * RPB) {
        __syncthreads();
        int rows = min(RPB, N - base);
        for (int i = tid; i < rows * FIN; i += 256) {
            float v = x[(long long)base * FIN + i];
            xs[i] = RELU ? fmaxf(v, 0.0f) : v;
        }
        __syncthreads();
        float4 a0 = {0, 0, 0, 0}, a1 = {0, 0, 0, 0}, a2 = {0, 0, 0, 0}, a3 = {0, 0, 0, 0};
#pragma unroll 8
        for (int k = 0; k < FIN; k++) {
            float4 w = *(const float4*)&Ws[k * FOUT + cq * 4];
            float x0 = xs[(r0 + 0) * FIN + k];
            float x1 = xs[(r0 + 1) * FIN + k];
            float x2 = xs[(r0 + 2) * FIN + k];
            float x3 = xs[(r0 + 3) * FIN + k];
            a0.x += x0 * w.x; a0.y += x0 * w.y; a0.z += x0 * w.z; a0.w += x0 * w.w;
            a1.x += x1 * w.x; a1.y += x1 * w.y; a1.z += x1 * w.z; a1.w += x1 * w.w;
            a2.x += x2 * w.x; a2.y += x2 * w.y; a2.z += x2 * w.z; a2.w += x2 * w.w;
            a3.x += x3 * w.x; a3.y += x3 * w.y; a3.z += x3 * w.z; a3.w += x3 * w.w;
        }
        if (base + r0 + 0 < N) *(float4*)&h[(long long)(base + r0 + 0) * FOUT + cq * 4] = a0;
        if (base + r0 + 1 < N) *(float4*)&h[(long long)(base + r0 + 1) * FOUT + cq * 4] = a1;
        if (base + r0 + 2 < N) *(float4*)&h[(long long)(base + r0 + 2) * FOUT + cq * 4] = a2;
        if (base + r0 + 3 < N) *(float4*)&h[(long long)(base + r0 + 3) * FOUT + cq * 4] = a3;
    }
}

// ---------------------------------------------------------------------------
// out[i] = h[i] * dinv[i]^2 + b   (self-loop term + bias; initializes out)
template <int F>
__global__ void k_selfinit(const float* __restrict__ h, const float* __restrict__ dinv,
                           const float* __restrict__ b, float* __restrict__ out, int N) {
    constexpr int Q = F / 4;
    int total = N * Q;
    int stride = gridDim.x * blockDim.x;
    for (int t = blockIdx.x * blockDim.x + threadIdx.x; t < total; t += stride) {
        int node = t / Q, q = t % Q;
        float di = dinv[node];
        float n2 = di * di;
        float4 v = *(const float4*)&h[(long long)node * F + q * 4];
        float4 bb = *(const float4*)&b[q * 4];
        float4 o = {v.x * n2 + bb.x, v.y * n2 + bb.y, v.z * n2 + bb.z, v.w * n2 + bb.w};
        *(float4*)&out[(long long)node * F + q * 4] = o;
    }
}

// ---------------------------------------------------------------------------
// Edge scatter: out[dst] += h[src] * dinv[src]*dinv[dst]
// 16-byte vectorized reduction (no return) — 4x fewer atomics.
// F/4 consecutive threads per edge -> coalesced h[src] row read.
template <int F>
__global__ void k_edges(const int* __restrict__ src, const int* __restrict__ dst,
                        const float* __restrict__ h, const float* __restrict__ dinv,
                        float* __restrict__ out, int E) {
    constexpr int Q = F / 4;
    long long total = (long long)E * Q;
    long long stride = (long long)gridDim.x * blockDim.x;
    for (long long t = (long long)blockIdx.x * blockDim.x + threadIdx.x; t < total; t += stride) {
        int e = (int)(t / Q);
        int q = (int)(t % Q);
        int si = src[e];
        int di = dst[e];
        float nrm = dinv[si] * dinv[di];
        float4 v = *(const float4*)&h[(long long)si * F + q * 4];
        float* p = &out[(long long)di * F + q * 4];
        asm volatile("red.global.add.v4.f32 [%0], {%1,%2,%3,%4};"
                     :: "l"(p), "f"(v.x * nrm), "f"(v.y * nrm), "f"(v.z * nrm), "f"(v.w * nrm)
                     : "memory");
    }
}

// ---------------------------------------------------------------------------
// Pooling: max + sum into embed rows (192 cols). Values are post-ReLU (>= 0),
// so atomicMax on int bit pattern is order-preserving and init-0 matches the
// empty-segment guard of the reference.
template <int F>
__global__ void k_pool(const float* __restrict__ x, const int* __restrict__ batch,
                       float* __restrict__ embed, int N, int mxcol, int mncol) {
    int total = N * F;
    int stride = gridDim.x * blockDim.x;
    for (int t = blockIdx.x * blockDim.x + threadIdx.x; t < total; t += stride) {
        int node = t / F, f = t % F;
        float v = fmaxf(x[t], 0.0f);  // ReLU fused here
        int g = batch[node];
        float* row = &embed[(long long)g * 192];
        atomicMax((int*)&row[mxcol + f], __float_as_int(v));
        atomicAdd(&row[mncol + f], v);
    }
}

__global__ void k_cnt(const int* __restrict__ batch, float* cnt, int N) {
    int stride = gridDim.x * blockDim.x;
    for (int i = blockIdx.x * blockDim.x + threadIdx.x; i < N; i += stride)
        atomicAdd(&cnt[batch[i]], 1.0f);
}

__global__ void k_finalize(float* embed, const float* __restrict__ cnt) {
    int i = blockIdx.x * blockDim.x + threadIdx.x;
    if (i >= NG * 192) return;
    int g = i / 192, col = i % 192;
    if (col >= 64 && col < 128) embed[i] /= fmaxf(cnt[g], 1.0f);          // c mean
    else if (col >= 160) embed[i] /= fmaxf(cnt[NG + g], 1.0f);           // s mean
}

// ---------------------------------------------------------------------------
// dense = relu(embed @ Wd + bd); out = dense @ Wo + bo. One block per graph.
__global__ void k_dense(const float* __restrict__ embed, const float* __restrict__ Wd,
                        const float* __restrict__ bd, const float* __restrict__ Wo,
                        const float* __restrict__ bo, float* __restrict__ out) {
    __shared__ float es[192];
    __shared__ float red[4];
    int g = blockIdx.x, tid = threadIdx.x;
    for (int i = tid; i < 192; i += 128) es[i] = embed[(long long)g * 192 + i];
    __syncthreads();
    float a = bd[tid];
#pragma unroll 8
    for (int k = 0; k < 192; k++) a += es[k] * Wd[k * 128 + tid];
    a = fmaxf(a, 0.0f);
    float v = a * Wo[tid];
#pragma unroll
    for (int o = 16; o > 0; o >>= 1) v += __shfl_down_sync(0xffffffffu, v, o);
    if ((tid & 31) == 0) red[tid >> 5] = v;
    __syncthreads();
    if (tid == 0) out[g] = red[0] + red[1] + red[2] + red[3] + bo[0];
}

// ---------------------------------------------------------------------------
extern "C" void kernel_launch(void* const* d_in, const int* in_sizes, int n_in,
                              void* d_out, int out_size) {
    const float* c       = (const float*)d_in[0];
    const int*   c_edge  = (const int*)d_in[1];
    const int*   c_batch = (const int*)d_in[2];
    const float* s       = (const float*)d_in[3];
    const int*   s_edge  = (const int*)d_in[4];
    const int*   s_batch = (const int*)d_in[5];
    const float* Wc0 = (const float*)d_in[6],  *bc0 = (const float*)d_in[7];
    const float* Wc1 = (const float*)d_in[8],  *bc1 = (const float*)d_in[9];
    const float* Wc2 = (const float*)d_in[10], *bc2 = (const float*)d_in[11];
    const float* Ws0 = (const float*)d_in[12], *bs0 = (const float*)d_in[13];
    const float* Ws1 = (const float*)d_in[14], *bs1 = (const float*)d_in[15];
    const float* Ws2 = (const float*)d_in[16], *bs2 = (const float*)d_in[17];
    const float* Wd  = (const float*)d_in[18], *bd  = (const float*)d_in[19];
    const float* Wo  = (const float*)d_in[20], *bo  = (const float*)d_in[21];

    int Nc = in_sizes[0] / 64;
    int Ec = in_sizes[1] / 2;
    int Ns = in_sizes[3] / 64;
    int Es = in_sizes[4] / 2;

    float* out   = (float*)d_out;
    float* embed = out + NG;  // [NG, 192]

    float *bufA, *bufB, *dinv, *cnt;
    cudaGetSymbolAddress((void**)&bufA, g_bufA);
    cudaGetSymbolAddress((void**)&bufB, g_bufB);
    cudaGetSymbolAddress((void**)&dinv, g_dinv);
    cudaGetSymbolAddress((void**)&cnt, g_cnt);

    const int T = 256;
    const int EDGE_BLKS = 2368;  // 148 SMs * 16

    // Init accumulators
    k_fill<<<(NG * 192 + T - 1) / T, T>>>(embed, 0.0f, NG * 192);
    k_fill<<<(2 * NG + T - 1) / T, T>>>(cnt, 0.0f, 2 * NG);

    // ================= c branch (F=64 -> 64 -> 64 -> 64) =================
    k_fill<<<(Nc + T - 1) / T, T>>>(dinv, 1.0f, Nc);           // self loops
    k_deg<<<1184, T>>>(c_edge + Ec, Ec, dinv);
    k_rsqrt<<<(Nc + T - 1) / T, T>>>(dinv, Nc);

    int gemmB64 = (Nc + 63) / 64;
    int siB64 = (Nc * 16 + T - 1) / T;

    k_gemm<64, 64, false><<<gemmB64, T>>>(c, Wc0, bufA, Nc);
    k_selfinit<64><<<siB64, T>>>(bufA, dinv, bc0, bufB, Nc);
    k_edges<64><<<EDGE_BLKS, T>>>(c_edge, c_edge + Ec, bufA, dinv, bufB, Ec);

    k_gemm<64, 64, true><<<gemmB64, T>>>(bufB, Wc1, bufA, Nc);
    k_selfinit<64><<<siB64, T>>>(bufA, dinv, bc1, bufB, Nc);
    k_edges<64><<<EDGE_BLKS, T>>>(c_edge, c_edge + Ec, bufA, dinv, bufB, Ec);

    k_gemm<64, 64, true><<<gemmB64, T>>>(bufB, Wc2, bufA, Nc);
    k_selfinit<64><<<siB64, T>>>(bufA, dinv, bc2, bufB, Nc);
    k_edges<64><<<EDGE_BLKS, T>>>(c_edge, c_edge + Ec, bufA, dinv, bufB, Ec);

    k_pool<64><<<(Nc * 64 + T - 1) / T, T>>>(bufB, c_batch, embed, Nc, 0, 64);
    k_cnt<<<(Nc + T - 1) / T, T>>>(c_batch, cnt, Nc);

    // ================= s branch (F=64 -> 32 -> 32 -> 32) =================
    k_fill<<<(Ns + T - 1) / T, T>>>(dinv, 1.0f, Ns);
    k_deg<<<1184, T>>>(s_edge + Es, Es, dinv);
    k_rsqrt<<<(Ns + T - 1) / T, T>>>(dinv, Ns);

    int gemmB128 = (Ns + 127) / 128;
    int siB32 = (Ns * 8 + T - 1) / T;

    k_gemm<64, 32, false><<<gemmB128, T>>>(s, Ws0, bufA, Ns);
    k_selfinit<32><<<siB32, T>>>(bufA, dinv, bs0, bufB, Ns);
    k_edges<32><<<EDGE_BLKS, T>>>(s_edge, s_edge + Es, bufA, dinv, bufB, Es);

    k_gemm<32, 32, true><<<gemmB128, T>>>(bufB, Ws1, bufA, Ns);
    k_selfinit<32><<<siB32, T>>>(bufA, dinv, bs1, bufB, Ns);
    k_edges<32><<<EDGE_BLKS, T>>>(s_edge, s_edge + Es, bufA, dinv, bufB, Es);

    k_gemm<32, 32, true><<<gemmB128, T>>>(bufB, Ws2, bufA, Ns);
    k_selfinit<32><<<siB32, T>>>(bufA, dinv, bs2, bufB, Ns);
    k_edges<32><<<EDGE_BLKS, T>>>(s_edge, s_edge + Es, bufA, dinv, bufB, Es);

    k_pool<32><<<(Ns * 32 + T - 1) / T, T>>>(bufB, s_batch, embed, Ns, 128, 160);
    k_cnt<<<(Ns + T - 1) / T, T>>>(s_batch, cnt + NG, Ns);

    // ================= head =================
    k_finalize<<<(NG * 192 + T - 1) / T, T>>>(embed, cnt);
    k_dense<<<NG, 128>>>(embed, Wd, bd, Wo, bo, out);
}

// round 2
// speedup vs baseline: 1.2802x; 1.2802x over previous
#include <cuda_runtime.h>

#define NG 2048
static const int NMAX = 100000;
static const int EMAX = 1250000;

// Scratch (device globals — no allocations allowed)
__device__ __align__(16) float g_bufA[NMAX * 64];   // hs = h * dinv[row]
__device__ __align__(16) float g_bufB[NMAX * 64];   // conv output (pre-relu)
__device__ float g_dinv[NMAX];
__device__ int   g_cnt[NMAX];
__device__ int   g_rowptr[NMAX + 1];
__device__ int   g_cursor[NMAX + 1];
__device__ int   g_perm[EMAX];
__device__ int   g_bsums[256];

// ---------------------------------------------------------------------------
__global__ void k_zero_i(int* p, int n) {
    int i = blockIdx.x * blockDim.x + threadIdx.x;
    if (i < n) p[i] = 0;
}

__global__ void k_count(const int* __restrict__ dst, int E, int* cnt) {
    int stride = gridDim.x * blockDim.x;
    for (int i = blockIdx.x * blockDim.x + threadIdx.x; i < E; i += stride)
        atomicAdd(&cnt[dst[i]], 1);
}

// dinv[i] = rsqrt(1 + in_degree)
__global__ void k_dinv(const int* __restrict__ cnt, float* dinv, int n) {
    int i = blockIdx.x * blockDim.x + threadIdx.x;
    if (i < n) dinv[i] = rsqrtf(1.0f + (float)cnt[i]);
}

// ---- block scan (1024 wide) for CSR rowptr -------------------------------
__global__ void k_scan1(const int* __restrict__ cnt, int* rowptr1, int* bsums, int n) {
    __shared__ int sh[1024];
    int i = blockIdx.x * 1024 + threadIdx.x;
    sh[threadIdx.x] = (i < n) ? cnt[i] : 0;
    __syncthreads();
    for (int off = 1; off < 1024; off <<= 1) {
        int t = (threadIdx.x >= off) ? sh[threadIdx.x - off] : 0;
        __syncthreads();
        sh[threadIdx.x] += t;
        __syncthreads();
    }
    if (i < n) rowptr1[i] = sh[threadIdx.x];
    if (threadIdx.x == 1023) bsums[blockIdx.x] = sh[1023];
}

__global__ void k_scan2(int* bsums, int nb) {
    if (threadIdx.x == 0 && blockIdx.x == 0) {
        int run = 0;
        for (int b = 0; b < nb; b++) { int t = bsums[b]; bsums[b] = run; run += t; }
    }
}

// finalize rowptr (exclusive at [0..n], inclusive stored at +1) + init cursor
__global__ void k_scan3(int* rowptr, int* cursor, const int* __restrict__ bsums, int n) {
    int i = blockIdx.x * blockDim.x + threadIdx.x;
    if (i == 0) { rowptr[0] = 0; cursor[0] = 0; }
    if (i < n) {
        int v = rowptr[i + 1] + bsums[i >> 10];
        rowptr[i + 1] = v;
        cursor[i + 1] = v;
    }
}

__global__ void k_build(const int* __restrict__ src, const int* __restrict__ dst,
                        int* cursor, int* perm, int E) {
    int stride = gridDim.x * blockDim.x;
    for (int i = blockIdx.x * blockDim.x + threadIdx.x; i < E; i += stride) {
        int p = atomicAdd(&cursor[dst[i]], 1);
        perm[p] = src[i];
    }
}

// ---------------------------------------------------------------------------
// hs = (act(x) @ W) * dinv[row]   (W row-major [FIN, FOUT])
template <int FIN, int FOUT, bool RELU>
__global__ void k_gemm(const float* __restrict__ x, const float* __restrict__ W,
                       const float* __restrict__ dinv, float* __restrict__ h, int N) {
    constexpr int CQ = FOUT / 4;
    constexpr int RQ = 256 / CQ;
    constexpr int RPB = RQ * 4;
    __shared__ float Ws[FIN * FOUT];
    __shared__ float xs[RPB * FIN];
    int tid = threadIdx.x;
    for (int i = tid; i < FIN * FOUT; i += 256) Ws[i] = W[i];
    int cq = tid % CQ;
    int r0 = (tid / CQ) * 4;
    for (int base = blockIdx.x * RPB; base < N; base += gridDim.x * RPB) {
        __syncthreads();
        int rows = min(RPB, N - base);
        for (int i = tid; i < rows * FIN; i += 256) {
            float v = x[(long long)base * FIN + i];
            xs[i] = RELU ? fmaxf(v, 0.0f) : v;
        }
        __syncthreads();
        float4 a0 = {0,0,0,0}, a1 = {0,0,0,0}, a2 = {0,0,0,0}, a3 = {0,0,0,0};
#pragma unroll 8
        for (int k = 0; k < FIN; k++) {
            float4 w = *(const float4*)&Ws[k * FOUT + cq * 4];
            float x0 = xs[(r0 + 0) * FIN + k];
            float x1 = xs[(r0 + 1) * FIN + k];
            float x2 = xs[(r0 + 2) * FIN + k];
            float x3 = xs[(r0 + 3) * FIN + k];
            a0.x += x0 * w.x; a0.y += x0 * w.y; a0.z += x0 * w.z; a0.w += x0 * w.w;
            a1.x += x1 * w.x; a1.y += x1 * w.y; a1.z += x1 * w.z; a1.w += x1 * w.w;
            a2.x += x2 * w.x; a2.y += x2 * w.y; a2.z += x2 * w.z; a2.w += x2 * w.w;
            a3.x += x3 * w.x; a3.y += x3 * w.y; a3.z += x3 * w.z; a3.w += x3 * w.w;
        }
#pragma unroll
        for (int r = 0; r < 4; r++) {
            int row = base + r0 + r;
            if (row < N) {
                float dv = dinv[row];
                float4 a = (r == 0) ? a0 : (r == 1) ? a1 : (r == 2) ? a2 : a3;
                a.x *= dv; a.y *= dv; a.z *= dv; a.w *= dv;
                *(float4*)&h[(long long)row * FOUT + cq * 4] = a;
            }
        }
    }
}

// ---------------------------------------------------------------------------
// CSR aggregation, warp per node:
// out[d] = dinv[d] * (hs[d] + sum_{src in in(d)} hs[src]) + b
__global__ void k_agg64(const int* __restrict__ rowptr, const int* __restrict__ perm,
                        const float* __restrict__ hs, const float* __restrict__ dinv,
                        const float* __restrict__ b, float* __restrict__ out, int N) {
    int warp = (blockIdx.x * blockDim.x + threadIdx.x) >> 5;
    if (warp >= N) return;
    int lane = threadIdx.x & 31;
    const float2* H = (const float2*)hs;
    float2 acc = H[(long long)warp * 32 + lane];  // self term
    int lo = rowptr[warp], hi = rowptr[warp + 1];
    for (int base = lo; base < hi; base += 32) {
        int cnt = min(32, hi - base);
        int s = (lane < cnt) ? perm[base + lane] : 0;
        for (int j = 0; j < cnt; j++) {
            int sj = __shfl_sync(0xffffffffu, s, j);
            float2 v = H[(long long)sj * 32 + lane];
            acc.x += v.x; acc.y += v.y;
        }
    }
    float d = dinv[warp];
    float2 bb = ((const float2*)b)[lane];
    float2 o = {acc.x * d + bb.x, acc.y * d + bb.y};
    ((float2*)out)[(long long)warp * 32 + lane] = o;
}

__global__ void k_agg32(const int* __restrict__ rowptr, const int* __restrict__ perm,
                        const float* __restrict__ hs, const float* __restrict__ dinv,
                        const float* __restrict__ b, float* __restrict__ out, int N) {
    int warp = (blockIdx.x * blockDim.x + threadIdx.x) >> 5;
    if (warp >= N) return;
    int lane = threadIdx.x & 31;
    float acc = hs[(long long)warp * 32 + lane];
    int lo = rowptr[warp], hi = rowptr[warp + 1];
    for (int base = lo; base < hi; base += 32) {
        int cnt = min(32, hi - base);
        int s = (lane < cnt) ? perm[base + lane] : 0;
        for (int j = 0; j < cnt; j++) {
            int sj = __shfl_sync(0xffffffffu, s, j);
            acc += hs[(long long)sj * 32 + lane];
        }
    }
    out[(long long)warp * 32 + lane] = acc * dinv[warp] + b[lane];
}

// ---------------------------------------------------------------------------
// Atomic-free pooling: batch is sorted, one block per graph, blockDim = F.
template <int F>
__global__ void k_poolg(const float* __restrict__ x, const int* __restrict__ batch,
                        int N, float* __restrict__ embed, int mxcol, int mncol) {
    int g = blockIdx.x;
    int j = threadIdx.x;
    // lower_bound(batch, g) and lower_bound(batch, g+1)
    int lo = 0, hi = N;
    while (lo < hi) { int m = (lo + hi) >> 1; if (batch[m] < g) lo = m + 1; else hi = m; }
    int lo2 = lo, hi2 = N;
    while (lo2 < hi2) { int m = (lo2 + hi2) >> 1; if (batch[m] < g + 1) lo2 = m + 1; else hi2 = m; }
    float mx = 0.0f, sum = 0.0f;
    for (int r = lo; r < lo2; r++) {
        float v = fmaxf(x[(long long)r * F + j], 0.0f);  // ReLU fused
        mx = fmaxf(mx, v);
        sum += v;
    }
    float cnt = (float)(lo2 - lo);
    embed[(long long)g * 192 + mxcol + j] = mx;
    embed[(long long)g * 192 + mncol + j] = sum / fmaxf(cnt, 1.0f);
}

// ---------------------------------------------------------------------------
__global__ void k_dense(const float* __restrict__ embed, const float* __restrict__ Wd,
                        const float* __restrict__ bd, const float* __restrict__ Wo,
                        const float* __restrict__ bo, float* __restrict__ out) {
    __shared__ float es[192];
    __shared__ float red[4];
    int g = blockIdx.x, tid = threadIdx.x;
    for (int i = tid; i < 192; i += 128) es[i] = embed[(long long)g * 192 + i];
    __syncthreads();
    float a = bd[tid];
#pragma unroll 8
    for (int k = 0; k < 192; k++) a += es[k] * Wd[k * 128 + tid];
    a = fmaxf(a, 0.0f);
    float v = a * Wo[tid];
#pragma unroll
    for (int o = 16; o > 0; o >>= 1) v += __shfl_down_sync(0xffffffffu, v, o);
    if ((tid & 31) == 0) red[tid >> 5] = v;
    __syncthreads();
    if (tid == 0) out[g] = red[0] + red[1] + red[2] + red[3] + bo[0];
}

// ---------------------------------------------------------------------------
extern "C" void kernel_launch(void* const* d_in, const int* in_sizes, int n_in,
                              void* d_out, int out_size) {
    const float* c       = (const float*)d_in[0];
    const int*   c_edge  = (const int*)d_in[1];
    const int*   c_batch = (const int*)d_in[2];
    const float* s       = (const float*)d_in[3];
    const int*   s_edge  = (const int*)d_in[4];
    const int*   s_batch = (const int*)d_in[5];
    const float* Wc0 = (const float*)d_in[6],  *bc0 = (const float*)d_in[7];
    const float* Wc1 = (const float*)d_in[8],  *bc1 = (const float*)d_in[9];
    const float* Wc2 = (const float*)d_in[10], *bc2 = (const float*)d_in[11];
    const float* Ws0 = (const float*)d_in[12], *bs0 = (const float*)d_in[13];
    const float* Ws1 = (const float*)d_in[14], *bs1 = (const float*)d_in[15];
    const float* Ws2 = (const float*)d_in[16], *bs2 = (const float*)d_in[17];
    const float* Wd  = (const float*)d_in[18], *bd  = (const float*)d_in[19];
    const float* Wo  = (const float*)d_in[20], *bo  = (const float*)d_in[21];

    int Nc = in_sizes[0] / 64;
    int Ec = in_sizes[1] / 2;
    int Ns = in_sizes[3] / 64;
    int Es = in_sizes[4] / 2;

    float* out   = (float*)d_out;
    float* embed = out + NG;  // [NG, 192]

    float *bufA, *bufB, *dinv;
    int *cnt, *rowptr, *cursor, *perm, *bsums;
    cudaGetSymbolAddress((void**)&bufA, g_bufA);
    cudaGetSymbolAddress((void**)&bufB, g_bufB);
    cudaGetSymbolAddress((void**)&dinv, g_dinv);
    cudaGetSymbolAddress((void**)&cnt, g_cnt);
    cudaGetSymbolAddress((void**)&rowptr, g_rowptr);
    cudaGetSymbolAddress((void**)&cursor, g_cursor);
    cudaGetSymbolAddress((void**)&perm, g_perm);
    cudaGetSymbolAddress((void**)&bsums, g_bsums);

    const int T = 256;
    const int GS = 1184;  // grid-stride blocks

    // ================= c branch (F=64) =================
    {
        int N = Nc, E = Ec;
        const int* esrc = c_edge;
        const int* edst = c_edge + E;
        int nb = (N + 1023) / 1024;
        k_zero_i<<<(N + T - 1) / T, T>>>(cnt, N);
        k_count<<<GS, T>>>(edst, E, cnt);
        k_dinv<<<(N + T - 1) / T, T>>>(cnt, dinv, N);
        k_scan1<<<nb, 1024>>>(cnt, rowptr + 1, bsums, N);
        k_scan2<<<1, 32>>>(bsums, nb);
        k_scan3<<<(N + T - 1) / T, T>>>(rowptr, cursor, bsums, N);
        k_build<<<GS, T>>>(esrc, edst, cursor, perm, E);

        int gemmB = (N + 63) / 64;
        int aggB = (N * 32 + T - 1) / T;  // warp per node, 8 warps/block

        k_gemm<64, 64, false><<<gemmB, T>>>(c, Wc0, dinv, bufA, N);
        k_agg64<<<aggB, T>>>(rowptr, perm, bufA, dinv, bc0, bufB, N);
        k_gemm<64, 64, true><<<gemmB, T>>>(bufB, Wc1, dinv, bufA, N);
        k_agg64<<<aggB, T>>>(rowptr, perm, bufA, dinv, bc1, bufB, N);
        k_gemm<64, 64, true><<<gemmB, T>>>(bufB, Wc2, dinv, bufA, N);
        k_agg64<<<aggB, T>>>(rowptr, perm, bufA, dinv, bc2, bufB, N);

        k_poolg<64><<<NG, 64>>>(bufB, c_batch, N, embed, 0, 64);
    }

    // ================= s branch (F=32) =================
    {
        int N = Ns, E = Es;
        const int* esrc = s_edge;
        const int* edst = s_edge + E;
        int nb = (N + 1023) / 1024;
        k_zero_i<<<(N + T - 1) / T, T>>>(cnt, N);
        k_count<<<GS, T>>>(edst, E, cnt);
        k_dinv<<<(N + T - 1) / T, T>>>(cnt, dinv, N);
        k_scan1<<<nb, 1024>>>(cnt, rowptr + 1, bsums, N);
        k_scan2<<<1, 32>>>(bsums, nb);
        k_scan3<<<(N + T - 1) / T, T>>>(rowptr, cursor, bsums, N);
        k_build<<<GS, T>>>(esrc, edst, cursor, perm, E);

        int gemmB64 = (N + 63) / 64;
        int gemmB128 = (N + 127) / 128;
        int aggB = (N * 32 + T - 1) / T;

        k_gemm<64, 32, false><<<gemmB128, T>>>(s, Ws0, dinv, bufA, N);
        k_agg32<<<aggB, T>>>(rowptr, perm, bufA, dinv, bs0, bufB, N);
        k_gemm<32, 32, true><<<gemmB128, T>>>(bufB, Ws1, dinv, bufA, N);
        k_agg32<<<aggB, T>>>(rowptr, perm, bufA, dinv, bs1, bufB, N);
        k_gemm<32, 32, true><<<gemmB128, T>>>(bufB, Ws2, dinv, bufA, N);
        k_agg32<<<aggB, T>>>(rowptr, perm, bufA, dinv, bs2, bufB, N);
        (void)gemmB64;

        k_poolg<32><<<NG, 32>>>(bufB, s_batch, N, embed, 128, 160);
    }

    // ================= head =================
    k_dense<<<NG, 128>>>(embed, Wd, bd, Wo, bo, out);
}

// round 3
// speedup vs baseline: 1.3984x; 1.0923x over previous
#include <cuda_runtime.h>

#define NG 2048
static const int NMAX = 100000;
static const int EMAX = 1250000;

// Per-branch scratch (device globals — no allocations allowed)
__device__ __align__(16) float g_bufA_c[NMAX * 64];
__device__ __align__(16) float g_bufB_c[NMAX * 64];
__device__ __align__(16) float g_bufA_s[NMAX * 32];
__device__ __align__(16) float g_bufB_s[NMAX * 32];
__device__ float g_dinv_c[NMAX];
__device__ float g_dinv_s[NMAX];
__device__ int   g_cnt_c[NMAX];
__device__ int   g_cnt_s[NMAX];
__device__ int   g_rowptr_c[NMAX + 1];
__device__ int   g_rowptr_s[NMAX + 1];
__device__ int   g_cursor_c[NMAX + 1];
__device__ int   g_cursor_s[NMAX + 1];
__device__ int   g_perm_c[EMAX];
__device__ int   g_perm_s[EMAX];
__device__ int   g_bsums_c[128];
__device__ int   g_bsums_s[128];

// ---------------------------------------------------------------------------
__global__ void k_zero_i(int* p, int n) {
    int i = blockIdx.x * blockDim.x + threadIdx.x;
    if (i < n) p[i] = 0;
}

__global__ void k_count(const int* __restrict__ dst, int E, int* cnt) {
    int stride = gridDim.x * blockDim.x;
    for (int i = blockIdx.x * blockDim.x + threadIdx.x; i < E; i += stride)
        atomicAdd(&cnt[dst[i]], 1);
}

// ---- block scan (1024 wide) for CSR rowptr -------------------------------
__global__ void k_scan1(const int* __restrict__ cnt, int* rowptr1, int* bsums, int n) {
    __shared__ int sh[1024];
    int i = blockIdx.x * 1024 + threadIdx.x;
    sh[threadIdx.x] = (i < n) ? cnt[i] : 0;
    __syncthreads();
    for (int off = 1; off < 1024; off <<= 1) {
        int t = (threadIdx.x >= off) ? sh[threadIdx.x - off] : 0;
        __syncthreads();
        sh[threadIdx.x] += t;
        __syncthreads();
    }
    if (i < n) rowptr1[i] = sh[threadIdx.x];
    if (threadIdx.x == 1023) bsums[blockIdx.x] = sh[1023];
}

// parallel exclusive scan of block sums (nb <= 128)
__global__ void k_scan2(int* bsums, int nb) {
    __shared__ int sh[128];
    int t = threadIdx.x;
    int v = (t < nb) ? bsums[t] : 0;
    sh[t] = v;
    __syncthreads();
    for (int off = 1; off < 128; off <<= 1) {
        int u = (t >= off) ? sh[t - off] : 0;
        __syncthreads();
        sh[t] += u;
        __syncthreads();
    }
    if (t < nb) bsums[t] = sh[t] - v;  // exclusive
}

// finalize rowptr, init cursor, compute dinv = rsqrt(1 + in_degree)
__global__ void k_scan3(int* rowptr, int* cursor, const int* __restrict__ bsums,
                        const int* __restrict__ cnt, float* dinv, int n) {
    int i = blockIdx.x * blockDim.x + threadIdx.x;
    if (i == 0) { rowptr[0] = 0; cursor[0] = 0; }
    if (i < n) {
        int v = rowptr[i + 1] + bsums[i >> 10];
        rowptr[i + 1] = v;
        cursor[i + 1] = v;
        dinv[i] = rsqrtf(1.0f + (float)cnt[i]);
    }
}

__global__ void k_build(const int* __restrict__ src, const int* __restrict__ dst,
                        int* cursor, int* perm, int E) {
    int stride = gridDim.x * blockDim.x;
    for (int i = blockIdx.x * blockDim.x + threadIdx.x; i < E; i += stride) {
        int p = atomicAdd(&cursor[dst[i]], 1);
        perm[p] = src[i];
    }
}

// ---------------------------------------------------------------------------
// hs = (act(x) @ W) * dinv[row]   (W row-major [FIN, FOUT])
template <int FIN, int FOUT, bool RELU>
__global__ void k_gemm(const float* __restrict__ x, const float* __restrict__ W,
                       const float* __restrict__ dinv, float* __restrict__ h, int N) {
    constexpr int CQ = FOUT / 4;
    constexpr int RQ = 256 / CQ;
    constexpr int RPB = RQ * 4;
    __shared__ float Ws[FIN * FOUT];
    __shared__ float xs[RPB * FIN];
    int tid = threadIdx.x;
    for (int i = tid; i < FIN * FOUT; i += 256) Ws[i] = W[i];
    int cq = tid % CQ;
    int r0 = (tid / CQ) * 4;
    for (int base = blockIdx.x * RPB; base < N; base += gridDim.x * RPB) {
        __syncthreads();
        int rows = min(RPB, N - base);
        for (int i = tid; i < rows * FIN; i += 256) {
            float v = x[(long long)base * FIN + i];
            xs[i] = RELU ? fmaxf(v, 0.0f) : v;
        }
        __syncthreads();
        float4 a0 = {0,0,0,0}, a1 = {0,0,0,0}, a2 = {0,0,0,0}, a3 = {0,0,0,0};
#pragma unroll 8
        for (int k = 0; k < FIN; k++) {
            float4 w = *(const float4*)&Ws[k * FOUT + cq * 4];
            float x0 = xs[(r0 + 0) * FIN + k];
            float x1 = xs[(r0 + 1) * FIN + k];
            float x2 = xs[(r0 + 2) * FIN + k];
            float x3 = xs[(r0 + 3) * FIN + k];
            a0.x += x0 * w.x; a0.y += x0 * w.y; a0.z += x0 * w.z; a0.w += x0 * w.w;
            a1.x += x1 * w.x; a1.y += x1 * w.y; a1.z += x1 * w.z; a1.w += x1 * w.w;
            a2.x += x2 * w.x; a2.y += x2 * w.y; a2.z += x2 * w.z; a2.w += x2 * w.w;
            a3.x += x3 * w.x; a3.y += x3 * w.y; a3.z += x3 * w.z; a3.w += x3 * w.w;
        }
#pragma unroll
        for (int r = 0; r < 4; r++) {
            int row = base + r0 + r;
            if (row < N) {
                float dv = dinv[row];
                float4 a = (r == 0) ? a0 : (r == 1) ? a1 : (r == 2) ? a2 : a3;
                a.x *= dv; a.y *= dv; a.z *= dv; a.w *= dv;
                *(float4*)&h[(long long)row * FOUT + cq * 4] = a;
            }
        }
    }
}

// ---------------------------------------------------------------------------
// CSR aggregation, warp per node:
// out[d] = dinv[d] * (hs[d] + sum_{src in in(d)} hs[src]) + b
__global__ void k_agg64(const int* __restrict__ rowptr, const int* __restrict__ perm,
                        const float* __restrict__ hs, const float* __restrict__ dinv,
                        const float* __restrict__ b, float* __restrict__ out, int N) {
    int warp = (blockIdx.x * blockDim.x + threadIdx.x) >> 5;
    if (warp >= N) return;
    int lane = threadIdx.x & 31;
    const float2* H = (const float2*)hs;
    float2 acc = H[(long long)warp * 32 + lane];  // self term
    int lo = rowptr[warp], hi = rowptr[warp + 1];
    for (int base = lo; base < hi; base += 32) {
        int cnt = min(32, hi - base);
        int s = (lane < cnt) ? perm[base + lane] : 0;
        for (int j = 0; j < cnt; j++) {
            int sj = __shfl_sync(0xffffffffu, s, j);
            float2 v = H[(long long)sj * 32 + lane];
            acc.x += v.x; acc.y += v.y;
        }
    }
    float d = dinv[warp];
    float2 bb = ((const float2*)b)[lane];
    float2 o = {acc.x * d + bb.x, acc.y * d + bb.y};
    ((float2*)out)[(long long)warp * 32 + lane] = o;
}

__global__ void k_agg32(const int* __restrict__ rowptr, const int* __restrict__ perm,
                        const float* __restrict__ hs, const float* __restrict__ dinv,
                        const float* __restrict__ b, float* __restrict__ out, int N) {
    int warp = (blockIdx.x * blockDim.x + threadIdx.x) >> 5;
    if (warp >= N) return;
    int lane = threadIdx.x & 31;
    float acc = hs[(long long)warp * 32 + lane];
    int lo = rowptr[warp], hi = rowptr[warp + 1];
    for (int base = lo; base < hi; base += 32) {
        int cnt = min(32, hi - base);
        int s = (lane < cnt) ? perm[base + lane] : 0;
        for (int j = 0; j < cnt; j++) {
            int sj = __shfl_sync(0xffffffffu, s, j);
            acc += hs[(long long)sj * 32 + lane];
        }
    }
    out[(long long)warp * 32 + lane] = acc * dinv[warp] + b[lane];
}

// ---------------------------------------------------------------------------
// Atomic-free pooling: batch is sorted, one block per graph, blockDim = F.
template <int F>
__global__ void k_poolg(const float* __restrict__ x, const int* __restrict__ batch,
                        int N, float* __restrict__ embed, int mxcol, int mncol) {
    int g = blockIdx.x;
    int j = threadIdx.x;
    int lo = 0, hi = N;
    while (lo < hi) { int m = (lo + hi) >> 1; if (batch[m] < g) lo = m + 1; else hi = m; }
    int lo2 = lo, hi2 = N;
    while (lo2 < hi2) { int m = (lo2 + hi2) >> 1; if (batch[m] < g + 1) lo2 = m + 1; else hi2 = m; }
    float mx = 0.0f, sum = 0.0f;
    for (int r = lo; r < lo2; r++) {
        float v = fmaxf(x[(long long)r * F + j], 0.0f);  // ReLU fused
        mx = fmaxf(mx, v);
        sum += v;
    }
    float cnt = (float)(lo2 - lo);
    embed[(long long)g * 192 + mxcol + j] = mx;
    embed[(long long)g * 192 + mncol + j] = sum / fmaxf(cnt, 1.0f);
}

// ---------------------------------------------------------------------------
__global__ void k_dense(const float* __restrict__ embed, const float* __restrict__ Wd,
                        const float* __restrict__ bd, const float* __restrict__ Wo,
                        const float* __restrict__ bo, float* __restrict__ out) {
    __shared__ float es[192];
    __shared__ float red[4];
    int g = blockIdx.x, tid = threadIdx.x;
    for (int i = tid; i < 192; i += 128) es[i] = embed[(long long)g * 192 + i];
    __syncthreads();
    float a = bd[tid];
#pragma unroll 8
    for (int k = 0; k < 192; k++) a += es[k] * Wd[k * 128 + tid];
    a = fmaxf(a, 0.0f);
    float v = a * Wo[tid];
#pragma unroll
    for (int o = 16; o > 0; o >>= 1) v += __shfl_down_sync(0xffffffffu, v, o);
    if ((tid & 31) == 0) red[tid >> 5] = v;
    __syncthreads();
    if (tid == 0) out[g] = red[0] + red[1] + red[2] + red[3] + bo[0];
}

// ---------------------------------------------------------------------------
static void run_csr(const int* edst, int N, int E, int* cnt, int* rowptr, int* cursor,
                    float* dinv, int* bsums, const int* esrc, int* perm, cudaStream_t st) {
    const int T = 256;
    const int GS = 1184;
    int nb = (N + 1023) / 1024;
    k_zero_i<<<(N + T - 1) / T, T, 0, st>>>(cnt, N);
    k_count<<<GS, T, 0, st>>>(edst, E, cnt);
    k_scan1<<<nb, 1024, 0, st>>>(cnt, rowptr + 1, bsums, N);
    k_scan2<<<1, 128, 0, st>>>(bsums, nb);
    k_scan3<<<(N + T - 1) / T, T, 0, st>>>(rowptr, cursor, bsums, cnt, dinv, N);
    k_build<<<GS, T, 0, st>>>(esrc, edst, cursor, perm, E);
}

extern "C" void kernel_launch(void* const* d_in, const int* in_sizes, int n_in,
                              void* d_out, int out_size) {
    const float* c       = (const float*)d_in[0];
    const int*   c_edge  = (const int*)d_in[1];
    const int*   c_batch = (const int*)d_in[2];
    const float* s       = (const float*)d_in[3];
    const int*   s_edge  = (const int*)d_in[4];
    const int*   s_batch = (const int*)d_in[5];
    const float* Wc0 = (const float*)d_in[6],  *bc0 = (const float*)d_in[7];
    const float* Wc1 = (const float*)d_in[8],  *bc1 = (const float*)d_in[9];
    const float* Wc2 = (const float*)d_in[10], *bc2 = (const float*)d_in[11];
    const float* Ws0 = (const float*)d_in[12], *bs0 = (const float*)d_in[13];
    const float* Ws1 = (const float*)d_in[14], *bs1 = (const float*)d_in[15];
    const float* Ws2 = (const float*)d_in[16], *bs2 = (const float*)d_in[17];
    const float* Wd  = (const float*)d_in[18], *bd  = (const float*)d_in[19];
    const float* Wo  = (const float*)d_in[20], *bo  = (const float*)d_in[21];

    int Nc = in_sizes[0] / 64;
    int Ec = in_sizes[1] / 2;
    int Ns = in_sizes[3] / 64;
    int Es = in_sizes[4] / 2;

    float* out   = (float*)d_out;
    float* embed = out + NG;  // [NG, 192]

    float *bufA_c, *bufB_c, *bufA_s, *bufB_s, *dinv_c, *dinv_s;
    int *cnt_c, *cnt_s, *rowptr_c, *rowptr_s, *cursor_c, *cursor_s;
    int *perm_c, *perm_s, *bsums_c, *bsums_s;
    cudaGetSymbolAddress((void**)&bufA_c, g_bufA_c);
    cudaGetSymbolAddress((void**)&bufB_c, g_bufB_c);
    cudaGetSymbolAddress((void**)&bufA_s, g_bufA_s);
    cudaGetSymbolAddress((void**)&bufB_s, g_bufB_s);
    cudaGetSymbolAddress((void**)&dinv_c, g_dinv_c);
    cudaGetSymbolAddress((void**)&dinv_s, g_dinv_s);
    cudaGetSymbolAddress((void**)&cnt_c, g_cnt_c);
    cudaGetSymbolAddress((void**)&cnt_s, g_cnt_s);
    cudaGetSymbolAddress((void**)&rowptr_c, g_rowptr_c);
    cudaGetSymbolAddress((void**)&rowptr_s, g_rowptr_s);
    cudaGetSymbolAddress((void**)&cursor_c, g_cursor_c);
    cudaGetSymbolAddress((void**)&cursor_s, g_cursor_s);
    cudaGetSymbolAddress((void**)&perm_c, g_perm_c);
    cudaGetSymbolAddress((void**)&perm_s, g_perm_s);
    cudaGetSymbolAddress((void**)&bsums_c, g_bsums_c);
    cudaGetSymbolAddress((void**)&bsums_s, g_bsums_s);

    // Lazy side-stream creation (infra only; does not change captured work
    // semantics — graph gets a fork/join of identical kernel nodes).
    static cudaStream_t s2 = nullptr;
    static cudaEvent_t evF = nullptr, evJ = nullptr;
    static bool tried = false;
    if (!tried) {
        tried = true;
        if (cudaStreamCreateWithFlags(&s2, cudaStreamNonBlocking) != cudaSuccess) s2 = nullptr;
        if (s2) {
            cudaEventCreateWithFlags(&evF, cudaEventDisableTiming);
            cudaEventCreateWithFlags(&evJ, cudaEventDisableTiming);
        }
    }
    cudaStream_t st0 = 0;
    cudaStream_t stS = s2 ? s2 : st0;
    bool fork = (s2 != nullptr);

    if (fork) {
        cudaEventRecord(evF, st0);
        cudaStreamWaitEvent(stS, evF, 0);
    }

    const int T = 256;

    // ================= c branch (F=64) on stream 0 =================
    {
        int N = Nc, E = Ec;
        run_csr(c_edge + E, N, E, cnt_c, rowptr_c, cursor_c, dinv_c, bsums_c, c_edge, perm_c, st0);
        int gemmB = (N + 63) / 64;
        int aggB = (N * 32 + T - 1) / T;
        k_gemm<64, 64, false><<<gemmB, T, 0, st0>>>(c, Wc0, dinv_c, bufA_c, N);
        k_agg64<<<aggB, T, 0, st0>>>(rowptr_c, perm_c, bufA_c, dinv_c, bc0, bufB_c, N);
        k_gemm<64, 64, true><<<gemmB, T, 0, st0>>>(bufB_c, Wc1, dinv_c, bufA_c, N);
        k_agg64<<<aggB, T, 0, st0>>>(rowptr_c, perm_c, bufA_c, dinv_c, bc1, bufB_c, N);
        k_gemm<64, 64, true><<<gemmB, T, 0, st0>>>(bufB_c, Wc2, dinv_c, bufA_c, N);
        k_agg64<<<aggB, T, 0, st0>>>(rowptr_c, perm_c, bufA_c, dinv_c, bc2, bufB_c, N);
        k_poolg<64><<<NG, 64, 0, st0>>>(bufB_c, c_batch, N, embed, 0, 64);
    }

    // ================= s branch (F=32) on side stream =================
    {
        int N = Ns, E = Es;
        run_csr(s_edge + E, N, E, cnt_s, rowptr_s, cursor_s, dinv_s, bsums_s, s_edge, perm_s, stS);
        int gemmB128 = (N + 127) / 128;
        int aggB = (N * 32 + T - 1) / T;
        k_gemm<64, 32, false><<<gemmB128, T, 0, stS>>>(s, Ws0, dinv_s, bufA_s, N);
        k_agg32<<<aggB, T, 0, stS>>>(rowptr_s, perm_s, bufA_s, dinv_s, bs0, bufB_s, N);
        k_gemm<32, 32, true><<<gemmB128, T, 0, stS>>>(bufB_s, Ws1, dinv_s, bufA_s, N);
        k_agg32<<<aggB, T, 0, stS>>>(rowptr_s, perm_s, bufA_s, dinv_s, bs1, bufB_s, N);
        k_gemm<32, 32, true><<<gemmB128, T, 0, stS>>>(bufB_s, Ws2, dinv_s, bufA_s, N);
        k_agg32<<<aggB, T, 0, stS>>>(rowptr_s, perm_s, bufA_s, dinv_s, bs2, bufB_s, N);
        k_poolg<32><<<NG, 32, 0, stS>>>(bufB_s, s_batch, N, embed, 128, 160);
    }

    if (fork) {
        cudaEventRecord(evJ, stS);
        cudaStreamWaitEvent(st0, evJ, 0);
    }

    // ================= head =================
    k_dense<<<NG, 128, 0, st0>>>(embed, Wd, bd, Wo, bo, out);
}

// round 5
// speedup vs baseline: 1.5643x; 1.1186x over previous
#include <cuda_runtime.h>
#include <cuda_fp16.h>

#define NG 2048
static const int NMAX = 100000;
static const int EMAX = 1250000;

// Per-branch scratch (device globals — no allocations allowed)
__device__ __align__(16) __half g_hsA_c[NMAX * 64];   // hs (fp16) c branch
__device__ __align__(16) float  g_bufB_c[NMAX * 64];  // conv out (fp32)
__device__ __align__(16) __half g_hsA_s[NMAX * 32];
__device__ __align__(16) float  g_bufB_s[NMAX * 32];
__device__ float g_dinv_c[NMAX];
__device__ float g_dinv_s[NMAX];
__device__ int   g_cnt_c[NMAX];
__device__ int   g_cnt_s[NMAX];
__device__ int   g_rowptr_c[NMAX + 1];
__device__ int   g_rowptr_s[NMAX + 1];
__device__ int   g_cursor_c[NMAX + 1];
__device__ int   g_cursor_s[NMAX + 1];
__device__ int   g_perm_c[EMAX];
__device__ int   g_perm_s[EMAX];
__device__ int   g_bsums_c[128];
__device__ int   g_bsums_s[128];

// ---------------------------------------------------------------------------
__global__ void k_zero_i(int* p, int n) {
    int i = blockIdx.x * blockDim.x + threadIdx.x;
    if (i < n) p[i] = 0;
}

__global__ void k_count(const int* __restrict__ dst, int E, int* cnt) {
    int stride = gridDim.x * blockDim.x;
    for (int i = blockIdx.x * blockDim.x + threadIdx.x; i < E; i += stride)
        atomicAdd(&cnt[dst[i]], 1);
}

// ---- block scan (1024 wide) for CSR rowptr -------------------------------
__global__ void k_scan1(const int* __restrict__ cnt, int* rowptr1, int* bsums, int n) {
    __shared__ int sh[1024];
    int i = blockIdx.x * 1024 + threadIdx.x;
    sh[threadIdx.x] = (i < n) ? cnt[i] : 0;
    __syncthreads();
    for (int off = 1; off < 1024; off <<= 1) {
        int t = (threadIdx.x >= off) ? sh[threadIdx.x - off] : 0;
        __syncthreads();
        sh[threadIdx.x] += t;
        __syncthreads();
    }
    if (i < n) rowptr1[i] = sh[threadIdx.x];
    if (threadIdx.x == 1023) bsums[blockIdx.x] = sh[1023];
}

__global__ void k_scan2(int* bsums, int nb) {
    __shared__ int sh[128];
    int t = threadIdx.x;
    int v = (t < nb) ? bsums[t] : 0;
    sh[t] = v;
    __syncthreads();
    for (int off = 1; off < 128; off <<= 1) {
        int u = (t >= off) ? sh[t - off] : 0;
        __syncthreads();
        sh[t] += u;
        __syncthreads();
    }
    if (t < nb) bsums[t] = sh[t] - v;  // exclusive
}

__global__ void k_scan3(int* rowptr, int* cursor, const int* __restrict__ bsums,
                        const int* __restrict__ cnt, float* dinv, int n) {
    int i = blockIdx.x * blockDim.x + threadIdx.x;
    if (i == 0) { rowptr[0] = 0; cursor[0] = 0; }
    if (i < n) {
        int v = rowptr[i + 1] + bsums[i >> 10];
        rowptr[i + 1] = v;
        cursor[i + 1] = v;
        dinv[i] = rsqrtf(1.0f + (float)cnt[i]);
    }
}

__global__ void k_build(const int* __restrict__ src, const int* __restrict__ dst,
                        int* cursor, int* perm, int E) {
    int stride = gridDim.x * blockDim.x;
    for (int i = blockIdx.x * blockDim.x + threadIdx.x; i < E; i += stride) {
        int p = atomicAdd(&cursor[dst[i]], 1);
        perm[p] = src[i];
    }
}

// ---------------------------------------------------------------------------
// hs(half) = (act(x) @ W) * dinv[row]   (W row-major [FIN, FOUT])
template <int FIN, int FOUT, bool RELU>
__global__ void k_gemm(const float* __restrict__ x, const float* __restrict__ W,
                       const float* __restrict__ dinv, __half* __restrict__ h, int N) {
    constexpr int CQ = FOUT / 4;
    constexpr int RQ = 256 / CQ;
    constexpr int RPB = RQ * 4;
    __shared__ float Ws[FIN * FOUT];
    __shared__ float xs[RPB * FIN];
    int tid = threadIdx.x;
    for (int i = tid; i < FIN * FOUT; i += 256) Ws[i] = W[i];
    int cq = tid % CQ;
    int r0 = (tid / CQ) * 4;
    for (int base = blockIdx.x * RPB; base < N; base += gridDim.x * RPB) {
        __syncthreads();
        int rows = min(RPB, N - base);
        for (int i = tid; i < rows * FIN; i += 256) {
            float v = x[(long long)base * FIN + i];
            xs[i] = RELU ? fmaxf(v, 0.0f) : v;
        }
        __syncthreads();
        float4 a0 = {0,0,0,0}, a1 = {0,0,0,0}, a2 = {0,0,0,0}, a3 = {0,0,0,0};
#pragma unroll 8
        for (int k = 0; k < FIN; k++) {
            float4 w = *(const float4*)&Ws[k * FOUT + cq * 4];
            float x0 = xs[(r0 + 0) * FIN + k];
            float x1 = xs[(r0 + 1) * FIN + k];
            float x2 = xs[(r0 + 2) * FIN + k];
            float x3 = xs[(r0 + 3) * FIN + k];
            a0.x += x0 * w.x; a0.y += x0 * w.y; a0.z += x0 * w.z; a0.w += x0 * w.w;
            a1.x += x1 * w.x; a1.y += x1 * w.y; a1.z += x1 * w.z; a1.w += x1 * w.w;
            a2.x += x2 * w.x; a2.y += x2 * w.y; a2.z += x2 * w.z; a2.w += x2 * w.w;
            a3.x += x3 * w.x; a3.y += x3 * w.y; a3.z += x3 * w.z; a3.w += x3 * w.w;
        }
#pragma unroll
        for (int r = 0; r < 4; r++) {
            int row = base + r0 + r;
            if (row < N) {
                float dv = dinv[row];
                float4 a = (r == 0) ? a0 : (r == 1) ? a1 : (r == 2) ? a2 : a3;
                __half2 h01 = __floats2half2_rn(a.x * dv, a.y * dv);
                __half2 h23 = __floats2half2_rn(a.z * dv, a.w * dv);
                uint2 pk = {*(unsigned*)&h01, *(unsigned*)&h23};
                *(uint2*)&h[(long long)row * FOUT + cq * 4] = pk;
            }
        }
    }
}

// ---------------------------------------------------------------------------
// CSR aggregation, warp per node, fp16 gather + fp32 accumulate:
// out[d] = dinv[d] * (hs[d] + sum_{src in in(d)} hs[src]) + b
__global__ void k_agg64(const int* __restrict__ rowptr, const int* __restrict__ perm,
                        const __half* __restrict__ hs, const float* __restrict__ dinv,
                        const float* __restrict__ b, float* __restrict__ out, int N) {
    int warp = (blockIdx.x * blockDim.x + threadIdx.x) >> 5;
    if (warp >= N) return;
    int lane = threadIdx.x & 31;
    const __half2* H = (const __half2*)hs;           // 32 half2 per row
    float2 acc = __half22float2(H[(long long)warp * 32 + lane]);  // self term
    int lo = rowptr[warp], hi = rowptr[warp + 1];
    for (int base = lo; base < hi; base += 32) {
        int cnt = min(32, hi - base);
        int s = (lane < cnt) ? perm[base + lane] : 0;
        for (int j = 0; j < cnt; j++) {
            int sj = __shfl_sync(0xffffffffu, s, j);
            float2 v = __half22float2(H[(long long)sj * 32 + lane]);
            acc.x += v.x; acc.y += v.y;
        }
    }
    float d = dinv[warp];
    float2 bb = ((const float2*)b)[lane];
    float2 o = {acc.x * d + bb.x, acc.y * d + bb.y};
    ((float2*)out)[(long long)warp * 32 + lane] = o;
}

__global__ void k_agg32(const int* __restrict__ rowptr, const int* __restrict__ perm,
                        const __half* __restrict__ hs, const float* __restrict__ dinv,
                        const float* __restrict__ b, float* __restrict__ out, int N) {
    int warp = (blockIdx.x * blockDim.x + threadIdx.x) >> 5;
    if (warp >= N) return;
    int lane = threadIdx.x & 31;
    float acc = __half2float(hs[(long long)warp * 32 + lane]);  // self
    int lo = rowptr[warp], hi = rowptr[warp + 1];
    for (int base = lo; base < hi; base += 32) {
        int cnt = min(32, hi - base);
        int s = (lane < cnt) ? perm[base + lane] : 0;
        for (int j = 0; j < cnt; j++) {
            int sj = __shfl_sync(0xffffffffu, s, j);
            acc += __half2float(hs[(long long)sj * 32 + lane]);
        }
    }
    out[(long long)warp * 32 + lane] = acc * dinv[warp] + b[lane];
}

// ---------------------------------------------------------------------------
// Atomic-free pooling: batch is sorted, one block per graph, blockDim = F.
template <int F>
__global__ void k_poolg(const float* __restrict__ x, const int* __restrict__ batch,
                        int N, float* __restrict__ embed, int mxcol, int mncol) {
    int g = blockIdx.x;
    int j = threadIdx.x;
    int lo = 0, hi = N;
    while (lo < hi) { int m = (lo + hi) >> 1; if (batch[m] < g) lo = m + 1; else hi = m; }
    int lo2 = lo, hi2 = N;
    while (lo2 < hi2) { int m = (lo2 + hi2) >> 1; if (batch[m] < g + 1) lo2 = m + 1; else hi2 = m; }
    float mx = 0.0f, sum = 0.0f;
    for (int r = lo; r < lo2; r++) {
        float v = fmaxf(x[(long long)r * F + j], 0.0f);  // ReLU fused
        mx = fmaxf(mx, v);
        sum += v;
    }
    float cnt = (float)(lo2 - lo);
    embed[(long long)g * 192 + mxcol + j] = mx;
    embed[(long long)g * 192 + mncol + j] = sum / fmaxf(cnt, 1.0f);
}

// ---------------------------------------------------------------------------
__global__ void k_dense(const float* __restrict__ embed, const float* __restrict__ Wd,
                        const float* __restrict__ bd, const float* __restrict__ Wo,
                        const float* __restrict__ bo, float* __restrict__ out) {
    __shared__ float es[192];
    __shared__ float red[4];
    int g = blockIdx.x, tid = threadIdx.x;
    for (int i = tid; i < 192; i += 128) es[i] = embed[(long long)g * 192 + i];
    __syncthreads();
    float a = bd[tid];
#pragma unroll 8
    for (int k = 0; k < 192; k++) a += es[k] * Wd[k * 128 + tid];
    a = fmaxf(a, 0.0f);
    float v = a * Wo[tid];
#pragma unroll
    for (int o = 16; o > 0; o >>= 1) v += __shfl_down_sync(0xffffffffu, v, o);
    if ((tid & 31) == 0) red[tid >> 5] = v;
    __syncthreads();
    if (tid == 0) out[g] = red[0] + red[1] + red[2] + red[3] + bo[0];
}

// ---------------------------------------------------------------------------
static void run_csr(const int* edst, int N, int E, int* cnt, int* rowptr, int* cursor,
                    float* dinv, int* bsums, const int* esrc, int* perm, cudaStream_t st) {
    const int T = 256;
    const int GS = 1184;
    int nb = (N + 1023) / 1024;
    k_zero_i<<<(N + T - 1) / T, T, 0, st>>>(cnt, N);
    k_count<<<GS, T, 0, st>>>(edst, E, cnt);
    k_scan1<<<nb, 1024, 0, st>>>(cnt, rowptr + 1, bsums, N);
    k_scan2<<<1, 128, 0, st>>>(bsums, nb);
    k_scan3<<<(N + T - 1) / T, T, 0, st>>>(rowptr, cursor, bsums, cnt, dinv, N);
    k_build<<<GS, T, 0, st>>>(esrc, edst, cursor, perm, E);
}

extern "C" void kernel_launch(void* const* d_in, const int* in_sizes, int n_in,
                              void* d_out, int out_size) {
    const float* c       = (const float*)d_in[0];
    const int*   c_edge  = (const int*)d_in[1];
    const int*   c_batch = (const int*)d_in[2];
    const float* s       = (const float*)d_in[3];
    const int*   s_edge  = (const int*)d_in[4];
    const int*   s_batch = (const int*)d_in[5];
    const float* Wc0 = (const float*)d_in[6],  *bc0 = (const float*)d_in[7];
    const float* Wc1 = (const float*)d_in[8],  *bc1 = (const float*)d_in[9];
    const float* Wc2 = (const float*)d_in[10], *bc2 = (const float*)d_in[11];
    const float* Ws0 = (const float*)d_in[12], *bs0 = (const float*)d_in[13];
    const float* Ws1 = (const float*)d_in[14], *bs1 = (const float*)d_in[15];
    const float* Ws2 = (const float*)d_in[16], *bs2 = (const float*)d_in[17];
    const float* Wd  = (const float*)d_in[18], *bd  = (const float*)d_in[19];
    const float* Wo  = (const float*)d_in[20], *bo  = (const float*)d_in[21];

    int Nc = in_sizes[0] / 64;
    int Ec = in_sizes[1] / 2;
    int Ns = in_sizes[3] / 64;
    int Es = in_sizes[4] / 2;

    float* out   = (float*)d_out;
    float* embed = out + NG;  // [NG, 192]

    __half *hsA_c, *hsA_s;
    float *bufB_c, *bufB_s, *dinv_c, *dinv_s;
    int *cnt_c, *cnt_s, *rowptr_c, *rowptr_s, *cursor_c, *cursor_s;
    int *perm_c, *perm_s, *bsums_c, *bsums_s;
    cudaGetSymbolAddress((void**)&hsA_c, g_hsA_c);
    cudaGetSymbolAddress((void**)&bufB_c, g_bufB_c);
    cudaGetSymbolAddress((void**)&hsA_s, g_hsA_s);
    cudaGetSymbolAddress((void**)&bufB_s, g_bufB_s);
    cudaGetSymbolAddress((void**)&dinv_c, g_dinv_c);
    cudaGetSymbolAddress((void**)&dinv_s, g_dinv_s);
    cudaGetSymbolAddress((void**)&cnt_c, g_cnt_c);
    cudaGetSymbolAddress((void**)&cnt_s, g_cnt_s);
    cudaGetSymbolAddress((void**)&rowptr_c, g_rowptr_c);
    cudaGetSymbolAddress((void**)&rowptr_s, g_rowptr_s);
    cudaGetSymbolAddress((void**)&cursor_c, g_cursor_c);
    cudaGetSymbolAddress((void**)&cursor_s, g_cursor_s);
    cudaGetSymbolAddress((void**)&perm_c, g_perm_c);
    cudaGetSymbolAddress((void**)&perm_s, g_perm_s);
    cudaGetSymbolAddress((void**)&bsums_c, g_bsums_c);
    cudaGetSymbolAddress((void**)&bsums_s, g_bsums_s);

    static cudaStream_t s2 = nullptr;
    static cudaEvent_t evF = nullptr, evJ = nullptr;
    static bool tried = false;
    if (!tried) {
        tried = true;
        if (cudaStreamCreateWithFlags(&s2, cudaStreamNonBlocking) != cudaSuccess) s2 = nullptr;
        if (s2) {
            cudaEventCreateWithFlags(&evF, cudaEventDisableTiming);
            cudaEventCreateWithFlags(&evJ, cudaEventDisableTiming);
        }
    }
    cudaStream_t st0 = 0;
    cudaStream_t stS = s2 ? s2 : st0;
    bool fork = (s2 != nullptr);

    if (fork) {
        cudaEventRecord(evF, st0);
        cudaStreamWaitEvent(stS, evF, 0);
    }

    const int T = 256;

    // ================= c branch (F=64) on stream 0 =================
    {
        int N = Nc, E = Ec;
        run_csr(c_edge + E, N, E, cnt_c, rowptr_c, cursor_c, dinv_c, bsums_c, c_edge, perm_c, st0);
        int gemmB = (N + 63) / 64;
        int aggB = (N * 32 + T - 1) / T;
        k_gemm<64, 64, false><<<gemmB, T, 0, st0>>>(c, Wc0, dinv_c, hsA_c, N);
        k_agg64<<<aggB, T, 0, st0>>>(rowptr_c, perm_c, hsA_c, dinv_c, bc0, bufB_c, N);
        k_gemm<64, 64, true><<<gemmB, T, 0, st0>>>(bufB_c, Wc1, dinv_c, hsA_c, N);
        k_agg64<<<aggB, T, 0, st0>>>(rowptr_c, perm_c, hsA_c, dinv_c, bc1, bufB_c, N);
        k_gemm<64, 64, true><<<gemmB, T, 0, st0>>>(bufB_c, Wc2, dinv_c, hsA_c, N);
        k_agg64<<<aggB, T, 0, st0>>>(rowptr_c, perm_c, hsA_c, dinv_c, bc2, bufB_c, N);
        k_poolg<64><<<NG, 64, 0, st0>>>(bufB_c, c_batch, N, embed, 0, 64);
    }

    // ================= s branch (F=32) on side stream =================
    {
        int N = Ns, E = Es;
        run_csr(s_edge + E, N, E, cnt_s, rowptr_s, cursor_s, dinv_s, bsums_s, s_edge, perm_s, stS);
        int gemmB128 = (N + 127) / 128;
        int aggB = (N * 32 + T - 1) / T;
        k_gemm<64, 32, false><<<gemmB128, T, 0, stS>>>(s, Ws0, dinv_s, hsA_s, N);
        k_agg32<<<aggB, T, 0, stS>>>(rowptr_s, perm_s, hsA_s, dinv_s, bs0, bufB_s, N);
        k_gemm<32, 32, true><<<gemmB128, T, 0, stS>>>(bufB_s, Ws1, dinv_s, hsA_s, N);
        k_agg32<<<aggB, T, 0, stS>>>(rowptr_s, perm_s, hsA_s, dinv_s, bs1, bufB_s, N);
        k_gemm<32, 32, true><<<gemmB128, T, 0, stS>>>(bufB_s, Ws2, dinv_s, hsA_s, N);
        k_agg32<<<aggB, T, 0, stS>>>(rowptr_s, perm_s, hsA_s, dinv_s, bs2, bufB_s, N);
        k_poolg<32><<<NG, 32, 0, stS>>>(bufB_s, s_batch, N, embed, 128, 160);
    }

    if (fork) {
        cudaEventRecord(evJ, stS);
        cudaStreamWaitEvent(st0, evJ, 0);
    }

    // ================= head =================
    k_dense<<<NG, 128, 0, st0>>>(embed, Wd, bd, Wo, bo, out);
}

// round 6
// speedup vs baseline: 1.8000x; 1.1507x over previous
#include <cuda_runtime.h>
#include <cuda_fp16.h>
#include <cstdint>

#define NG 2048
static const int NMAX = 100000;
static const int EMAX = 1250000;

// Per-branch scratch (device globals — no allocations allowed)
__device__ __align__(16) __half g_hsA_c[NMAX * 64];   // hs (fp16) c branch
__device__ __align__(16) float  g_bufB_c[NMAX * 64];  // conv out (fp32)
__device__ __align__(16) __half g_hsA_s[NMAX * 32];
__device__ __align__(16) float  g_bufB_s[NMAX * 32];
__device__ float g_dinv_c[NMAX];
__device__ float g_dinv_s[NMAX];
__device__ int   g_cnt_c[NMAX];
__device__ int   g_cnt_s[NMAX];
__device__ int   g_rowptr_c[NMAX + 1];
__device__ int   g_rowptr_s[NMAX + 1];
__device__ int   g_cursor_c[NMAX + 1];
__device__ int   g_cursor_s[NMAX + 1];
__device__ int   g_perm_c[EMAX];
__device__ int   g_perm_s[EMAX];
__device__ int   g_bsums_c[128];
__device__ int   g_bsums_s[128];

// ---------------------------------------------------------------------------
__global__ void k_zero_i(int* p, int n) {
    int i = blockIdx.x * blockDim.x + threadIdx.x;
    if (i < n) p[i] = 0;
}

__global__ void k_count(const int* __restrict__ dst, int E, int* cnt) {
    int stride = gridDim.x * blockDim.x;
    for (int i = blockIdx.x * blockDim.x + threadIdx.x; i < E; i += stride)
        atomicAdd(&cnt[dst[i]], 1);
}

__global__ void k_scan1(const int* __restrict__ cnt, int* rowptr1, int* bsums, int n) {
    __shared__ int sh[1024];
    int i = blockIdx.x * 1024 + threadIdx.x;
    sh[threadIdx.x] = (i < n) ? cnt[i] : 0;
    __syncthreads();
    for (int off = 1; off < 1024; off <<= 1) {
        int t = (threadIdx.x >= off) ? sh[threadIdx.x - off] : 0;
        __syncthreads();
        sh[threadIdx.x] += t;
        __syncthreads();
    }
    if (i < n) rowptr1[i] = sh[threadIdx.x];
    if (threadIdx.x == 1023) bsums[blockIdx.x] = sh[1023];
}

__global__ void k_scan2(int* bsums, int nb) {
    __shared__ int sh[128];
    int t = threadIdx.x;
    int v = (t < nb) ? bsums[t] : 0;
    sh[t] = v;
    __syncthreads();
    for (int off = 1; off < 128; off <<= 1) {
        int u = (t >= off) ? sh[t - off] : 0;
        __syncthreads();
        sh[t] += u;
        __syncthreads();
    }
    if (t < nb) bsums[t] = sh[t] - v;  // exclusive
}

__global__ void k_scan3(int* rowptr, int* cursor, const int* __restrict__ bsums,
                        const int* __restrict__ cnt, float* dinv, int n) {
    int i = blockIdx.x * blockDim.x + threadIdx.x;
    if (i == 0) { rowptr[0] = 0; cursor[0] = 0; }
    if (i < n) {
        int v = rowptr[i + 1] + bsums[i >> 10];
        rowptr[i + 1] = v;
        cursor[i + 1] = v;
        dinv[i] = rsqrtf(1.0f + (float)cnt[i]);
    }
}

__global__ void k_build(const int* __restrict__ src, const int* __restrict__ dst,
                        int* cursor, int* perm, int E) {
    int stride = gridDim.x * blockDim.x;
    for (int i = blockIdx.x * blockDim.x + threadIdx.x; i < E; i += stride) {
        int p = atomicAdd(&cursor[dst[i]], 1);
        perm[p] = src[i];
    }
}

// ---------------------------------------------------------------------------
// Tensor-core GEMM: hs(half) = (act(x) @ W) * dinv[row]
// mma.sync m16n8k16 f16*f16 -> f32. Block = 256 threads = 8 warps,
// tile M=128 rows; warp w owns rows [w*16, w*16+16) x all FOUT cols.
template <int FIN, int FOUT, bool RELU>
__global__ void k_gemm_mma(const float* __restrict__ x, const float* __restrict__ W,
                           const float* __restrict__ dinv, __half* __restrict__ h, int N) {
    constexpr int KC = FIN / 16;     // k chunks
    constexpr int NT = FOUT / 8;     // n tiles per warp
    constexpr int ASTR = FIN + 8;    // halves (16B-aligned stride)
    constexpr int BSTR = FOUT + 8;
    __shared__ __half As[128 * ASTR];
    __shared__ __half Bs[FIN * BSTR];
    int tid = threadIdx.x;
    int base = blockIdx.x * 128;

    // Load W (fp32 global) -> fp16 smem [FIN][BSTR]
    for (int i = tid; i < FIN * FOUT; i += 256) {
        int r = i / FOUT, cc = i % FOUT;
        Bs[r * BSTR + cc] = __float2half_rn(W[i]);
    }
    // Load x tile (fp32) -> fp16 smem [128][ASTR], ReLU fused, zero-fill OOB
    constexpr int PAIRS = 128 * FIN / 2;
    for (int p = tid; p < PAIRS; p += 256) {
        int r = p / (FIN / 2), cp = p % (FIN / 2);
        __half2 hv;
        int grow = base + r;
        if (grow < N) {
            float2 v = *(const float2*)&x[(long long)grow * FIN + cp * 2];
            if (RELU) { v.x = fmaxf(v.x, 0.0f); v.y = fmaxf(v.y, 0.0f); }
            hv = __floats2half2_rn(v.x, v.y);
        } else {
            hv = __floats2half2_rn(0.0f, 0.0f);
        }
        *(__half2*)&As[r * ASTR + cp * 2] = hv;
    }
    __syncthreads();

    int warp = tid >> 5, lane = tid & 31;
    float acc[NT][4];
#pragma unroll
    for (int nt = 0; nt < NT; nt++)
#pragma unroll
        for (int j = 0; j < 4; j++) acc[nt][j] = 0.0f;

    // A fragment base address (per ldmatrix.x4 recipe)
    uint32_t a_addr0 = (uint32_t)__cvta_generic_to_shared(
        &As[(warp * 16 + (lane & 15)) * ASTR + (lane >> 4) * 8]);
    uint32_t b_row = (lane & 15);

#pragma unroll
    for (int kc = 0; kc < KC; kc++) {
        uint32_t a0, a1, a2, a3;
        uint32_t aa = a_addr0 + kc * 16 * 2;  // advance 16 halves in k
        asm volatile("ldmatrix.sync.aligned.m8n8.x4.shared.b16 {%0,%1,%2,%3}, [%4];"
                     : "=r"(a0), "=r"(a1), "=r"(a2), "=r"(a3) : "r"(aa));
#pragma unroll
        for (int nt = 0; nt < NT; nt++) {
            uint32_t b0, b1;
            uint32_t ba = (uint32_t)__cvta_generic_to_shared(
                &Bs[(kc * 16 + b_row) * BSTR + nt * 8]);
            asm volatile("ldmatrix.sync.aligned.m8n8.x2.trans.shared.b16 {%0,%1}, [%2];"
                         : "=r"(b0), "=r"(b1) : "r"(ba));
            asm volatile(
                "mma.sync.aligned.m16n8k16.row.col.f32.f16.f16.f32 "
                "{%0,%1,%2,%3}, {%4,%5,%6,%7}, {%8,%9}, {%0,%1,%2,%3};"
                : "+f"(acc[nt][0]), "+f"(acc[nt][1]), "+f"(acc[nt][2]), "+f"(acc[nt][3])
                : "r"(a0), "r"(a1), "r"(a2), "r"(a3), "r"(b0), "r"(b1));
        }
    }

    // Epilogue: scale by dinv[row], pack fp16, store.
    int r0 = base + warp * 16 + (lane >> 2);
    int r1 = r0 + 8;
    float d0 = (r0 < N) ? dinv[r0] : 0.0f;
    float d1 = (r1 < N) ? dinv[r1] : 0.0f;
    int colb = (lane & 3) * 2;
#pragma unroll
    for (int nt = 0; nt < NT; nt++) {
        int col = nt * 8 + colb;
        if (r0 < N) {
            __half2 hv = __floats2half2_rn(acc[nt][0] * d0, acc[nt][1] * d0);
            *(__half2*)&h[(long long)r0 * FOUT + col] = hv;
        }
        if (r1 < N) {
            __half2 hv = __floats2half2_rn(acc[nt][2] * d1, acc[nt][3] * d1);
            *(__half2*)&h[(long long)r1 * FOUT + col] = hv;
        }
    }
}

// ---------------------------------------------------------------------------
// CSR aggregation, warp per node, fp16 gather + fp32 accumulate:
// out[d] = dinv[d] * (hs[d] + sum_{src in in(d)} hs[src]) + b
__global__ void k_agg64(const int* __restrict__ rowptr, const int* __restrict__ perm,
                        const __half* __restrict__ hs, const float* __restrict__ dinv,
                        const float* __restrict__ b, float* __restrict__ out, int N) {
    int warp = (blockIdx.x * blockDim.x + threadIdx.x) >> 5;
    if (warp >= N) return;
    int lane = threadIdx.x & 31;
    const __half2* H = (const __half2*)hs;
    float2 acc = __half22float2(H[(long long)warp * 32 + lane]);  // self term
    int lo = rowptr[warp], hi = rowptr[warp + 1];
    for (int base = lo; base < hi; base += 32) {
        int cnt = min(32, hi - base);
        int s = (lane < cnt) ? perm[base + lane] : 0;
        for (int j = 0; j < cnt; j++) {
            int sj = __shfl_sync(0xffffffffu, s, j);
            float2 v = __half22float2(H[(long long)sj * 32 + lane]);
            acc.x += v.x; acc.y += v.y;
        }
    }
    float d = dinv[warp];
    float2 bb = ((const float2*)b)[lane];
    float2 o = {acc.x * d + bb.x, acc.y * d + bb.y};
    ((float2*)out)[(long long)warp * 32 + lane] = o;
}

__global__ void k_agg32(const int* __restrict__ rowptr, const int* __restrict__ perm,
                        const __half* __restrict__ hs, const float* __restrict__ dinv,
                        const float* __restrict__ b, float* __restrict__ out, int N) {
    int warp = (blockIdx.x * blockDim.x + threadIdx.x) >> 5;
    if (warp >= N) return;
    int lane = threadIdx.x & 31;
    float acc = __half2float(hs[(long long)warp * 32 + lane]);  // self
    int lo = rowptr[warp], hi = rowptr[warp + 1];
    for (int base = lo; base < hi; base += 32) {
        int cnt = min(32, hi - base);
        int s = (lane < cnt) ? perm[base + lane] : 0;
        for (int j = 0; j < cnt; j++) {
            int sj = __shfl_sync(0xffffffffu, s, j);
            acc += __half2float(hs[(long long)sj * 32 + lane]);
        }
    }
    out[(long long)warp * 32 + lane] = acc * dinv[warp] + b[lane];
}

// ---------------------------------------------------------------------------
// Atomic-free pooling: batch is sorted, one block per graph, blockDim = F.
template <int F>
__global__ void k_poolg(const float* __restrict__ x, const int* __restrict__ batch,
                        int N, float* __restrict__ embed, int mxcol, int mncol) {
    int g = blockIdx.x;
    int j = threadIdx.x;
    int lo = 0, hi = N;
    while (lo < hi) { int m = (lo + hi) >> 1; if (batch[m] < g) lo = m + 1; else hi = m; }
    int lo2 = lo, hi2 = N;
    while (lo2 < hi2) { int m = (lo2 + hi2) >> 1; if (batch[m] < g + 1) lo2 = m + 1; else hi2 = m; }
    float mx = 0.0f, sum = 0.0f;
    for (int r = lo; r < lo2; r++) {
        float v = fmaxf(x[(long long)r * F + j], 0.0f);  // ReLU fused
        mx = fmaxf(mx, v);
        sum += v;
    }
    float cnt = (float)(lo2 - lo);
    embed[(long long)g * 192 + mxcol + j] = mx;
    embed[(long long)g * 192 + mncol + j] = sum / fmaxf(cnt, 1.0f);
}

// ---------------------------------------------------------------------------
__global__ void k_dense(const float* __restrict__ embed, const float* __restrict__ Wd,
                        const float* __restrict__ bd, const float* __restrict__ Wo,
                        const float* __restrict__ bo, float* __restrict__ out) {
    __shared__ float es[192];
    __shared__ float red[4];
    int g = blockIdx.x, tid = threadIdx.x;
    for (int i = tid; i < 192; i += 128) es[i] = embed[(long long)g * 192 + i];
    __syncthreads();
    float a = bd[tid];
#pragma unroll 8
    for (int k = 0; k < 192; k++) a += es[k] * Wd[k * 128 + tid];
    a = fmaxf(a, 0.0f);
    float v = a * Wo[tid];
#pragma unroll
    for (int o = 16; o > 0; o >>= 1) v += __shfl_down_sync(0xffffffffu, v, o);
    if ((tid & 31) == 0) red[tid >> 5] = v;
    __syncthreads();
    if (tid == 0) out[g] = red[0] + red[1] + red[2] + red[3] + bo[0];
}

// ---------------------------------------------------------------------------
static void run_csr(const int* edst, int N, int E, int* cnt, int* rowptr, int* cursor,
                    float* dinv, int* bsums, const int* esrc, int* perm, cudaStream_t st) {
    const int T = 256;
    const int GS = 1184;
    int nb = (N + 1023) / 1024;
    k_zero_i<<<(N + T - 1) / T, T, 0, st>>>(cnt, N);
    k_count<<<GS, T, 0, st>>>(edst, E, cnt);
    k_scan1<<<nb, 1024, 0, st>>>(cnt, rowptr + 1, bsums, N);
    k_scan2<<<1, 128, 0, st>>>(bsums, nb);
    k_scan3<<<(N + T - 1) / T, T, 0, st>>>(rowptr, cursor, bsums, cnt, dinv, N);
    k_build<<<GS, T, 0, st>>>(esrc, edst, cursor, perm, E);
}

extern "C" void kernel_launch(void* const* d_in, const int* in_sizes, int n_in,
                              void* d_out, int out_size) {
    const float* c       = (const float*)d_in[0];
    const int*   c_edge  = (const int*)d_in[1];
    const int*   c_batch = (const int*)d_in[2];
    const float* s       = (const float*)d_in[3];
    const int*   s_edge  = (const int*)d_in[4];
    const int*   s_batch = (const int*)d_in[5];
    const float* Wc0 = (const float*)d_in[6],  *bc0 = (const float*)d_in[7];
    const float* Wc1 = (const float*)d_in[8],  *bc1 = (const float*)d_in[9];
    const float* Wc2 = (const float*)d_in[10], *bc2 = (const float*)d_in[11];
    const float* Ws0 = (const float*)d_in[12], *bs0 = (const float*)d_in[13];
    const float* Ws1 = (const float*)d_in[14], *bs1 = (const float*)d_in[15];
    const float* Ws2 = (const float*)d_in[16], *bs2 = (const float*)d_in[17];
    const float* Wd  = (const float*)d_in[18], *bd  = (const float*)d_in[19];
    const float* Wo  = (const float*)d_in[20], *bo  = (const float*)d_in[21];

    int Nc = in_sizes[0] / 64;
    int Ec = in_sizes[1] / 2;
    int Ns = in_sizes[3] / 64;
    int Es = in_sizes[4] / 2;

    float* out   = (float*)d_out;
    float* embed = out + NG;  // [NG, 192]

    __half *hsA_c, *hsA_s;
    float *bufB_c, *bufB_s, *dinv_c, *dinv_s;
    int *cnt_c, *cnt_s, *rowptr_c, *rowptr_s, *cursor_c, *cursor_s;
    int *perm_c, *perm_s, *bsums_c, *bsums_s;
    cudaGetSymbolAddress((void**)&hsA_c, g_hsA_c);
    cudaGetSymbolAddress((void**)&bufB_c, g_bufB_c);
    cudaGetSymbolAddress((void**)&hsA_s, g_hsA_s);
    cudaGetSymbolAddress((void**)&bufB_s, g_bufB_s);
    cudaGetSymbolAddress((void**)&dinv_c, g_dinv_c);
    cudaGetSymbolAddress((void**)&dinv_s, g_dinv_s);
    cudaGetSymbolAddress((void**)&cnt_c, g_cnt_c);
    cudaGetSymbolAddress((void**)&cnt_s, g_cnt_s);
    cudaGetSymbolAddress((void**)&rowptr_c, g_rowptr_c);
    cudaGetSymbolAddress((void**)&rowptr_s, g_rowptr_s);
    cudaGetSymbolAddress((void**)&cursor_c, g_cursor_c);
    cudaGetSymbolAddress((void**)&cursor_s, g_cursor_s);
    cudaGetSymbolAddress((void**)&perm_c, g_perm_c);
    cudaGetSymbolAddress((void**)&perm_s, g_perm_s);
    cudaGetSymbolAddress((void**)&bsums_c, g_bsums_c);
    cudaGetSymbolAddress((void**)&bsums_s, g_bsums_s);

    static cudaStream_t s2 = nullptr;
    static cudaEvent_t evF = nullptr, evJ = nullptr;
    static bool tried = false;
    if (!tried) {
        tried = true;
        if (cudaStreamCreateWithFlags(&s2, cudaStreamNonBlocking) != cudaSuccess) s2 = nullptr;
        if (s2) {
            cudaEventCreateWithFlags(&evF, cudaEventDisableTiming);
            cudaEventCreateWithFlags(&evJ, cudaEventDisableTiming);
        }
    }
    cudaStream_t st0 = 0;
    cudaStream_t stS = s2 ? s2 : st0;
    bool fork = (s2 != nullptr);

    if (fork) {
        cudaEventRecord(evF, st0);
        cudaStreamWaitEvent(stS, evF, 0);
    }

    const int T = 256;

    // ================= c branch (F=64) on stream 0 =================
    {
        int N = Nc, E = Ec;
        run_csr(c_edge + E, N, E, cnt_c, rowptr_c, cursor_c, dinv_c, bsums_c, c_edge, perm_c, st0);
        int mmaB = (N + 127) / 128;
        int aggB = (N * 32 + T - 1) / T;
        k_gemm_mma<64, 64, false><<<mmaB, 256, 0, st0>>>(c, Wc0, dinv_c, hsA_c, N);
        k_agg64<<<aggB, T, 0, st0>>>(rowptr_c, perm_c, hsA_c, dinv_c, bc0, bufB_c, N);
        k_gemm_mma<64, 64, true><<<mmaB, 256, 0, st0>>>(bufB_c, Wc1, dinv_c, hsA_c, N);
        k_agg64<<<aggB, T, 0, st0>>>(rowptr_c, perm_c, hsA_c, dinv_c, bc1, bufB_c, N);
        k_gemm_mma<64, 64, true><<<mmaB, 256, 0, st0>>>(bufB_c, Wc2, dinv_c, hsA_c, N);
        k_agg64<<<aggB, T, 0, st0>>>(rowptr_c, perm_c, hsA_c, dinv_c, bc2, bufB_c, N);
        k_poolg<64><<<NG, 64, 0, st0>>>(bufB_c, c_batch, N, embed, 0, 64);
    }

    // ================= s branch (F=32) on side stream =================
    {
        int N = Ns, E = Es;
        run_csr(s_edge + E, N, E, cnt_s, rowptr_s, cursor_s, dinv_s, bsums_s, s_edge, perm_s, stS);
        int mmaB = (N + 127) / 128;
        int aggB = (N * 32 + T - 1) / T;
        k_gemm_mma<64, 32, false><<<mmaB, 256, 0, stS>>>(s, Ws0, dinv_s, hsA_s, N);
        k_agg32<<<aggB, T, 0, stS>>>(rowptr_s, perm_s, hsA_s, dinv_s, bs0, bufB_s, N);
        k_gemm_mma<32, 32, true><<<mmaB, 256, 0, stS>>>(bufB_s, Ws1, dinv_s, hsA_s, N);
        k_agg32<<<aggB, T, 0, stS>>>(rowptr_s, perm_s, hsA_s, dinv_s, bs1, bufB_s, N);
        k_gemm_mma<32, 32, true><<<mmaB, 256, 0, stS>>>(bufB_s, Ws2, dinv_s, hsA_s, N);
        k_agg32<<<aggB, T, 0, stS>>>(rowptr_s, perm_s, hsA_s, dinv_s, bs2, bufB_s, N);
        k_poolg<32><<<NG, 32, 0, stS>>>(bufB_s, s_batch, N, embed, 128, 160);
    }

    if (fork) {
        cudaEventRecord(evJ, stS);
        cudaStreamWaitEvent(st0, evJ, 0);
    }

    // ================= head =================
    k_dense<<<NG, 128, 0, st0>>>(embed, Wd, bd, Wo, bo, out);
}

// round 9
// speedup vs baseline: 1.8063x; 1.0035x over previous
#include <cuda_runtime.h>
#include <cuda_fp16.h>
#include <cstdint>

#define NG 2048
static const int NMAX = 100000;
static const int EMAX = 1250000;

// Per-branch scratch (device globals — no allocations allowed)
__device__ __align__(16) __half g_hs_c[NMAX * 64];   // gemm out (scaled, fp16)
__device__ __align__(16) __half g_hB_c[NMAX * 64];   // conv out (fp16)
__device__ __align__(16) __half g_hs_s[NMAX * 32];
__device__ __align__(16) __half g_hB_s[NMAX * 32];
__device__ float g_dinv_c[NMAX];
__device__ float g_dinv_s[NMAX];
__device__ int   g_cnt_c[NMAX];
__device__ int   g_cnt_s[NMAX];
__device__ int   g_start_c[NMAX];
__device__ int   g_start_s[NMAX];
__device__ int   g_cursor_c[NMAX];
__device__ int   g_cursor_s[NMAX];
__device__ int   g_perm_c[EMAX];
__device__ int   g_perm_s[EMAX];
__device__ int   g_tot_c;
__device__ int   g_tot_s;

// ---------------------------------------------------------------------------
__global__ void k_zero(int* cnt, int* tot, int n) {
    int i = blockIdx.x * blockDim.x + threadIdx.x;
    if (i < n) cnt[i] = 0;
    if (i == 0) *tot = 0;
}

__global__ void k_count(const int* __restrict__ dst, int E, int* cnt) {
    int stride = gridDim.x * blockDim.x;
    for (int i = blockIdx.x * blockDim.x + threadIdx.x; i < E; i += stride)
        atomicAdd(&cnt[dst[i]], 1);
}

// Warp-aggregated segment assignment: start[i] = contiguous slot of size cnt[i]
// (segment order arbitrary; CSR only needs per-node contiguity). Also dinv.
__global__ void k_offsets(const int* __restrict__ cnt, int* start, int* cursor,
                          float* dinv, int* tot, int n) {
    int i = blockIdx.x * blockDim.x + threadIdx.x;
    int lane = threadIdx.x & 31;
    int c = (i < n) ? cnt[i] : 0;
    // inclusive warp scan
    int inc = c;
#pragma unroll
    for (int off = 1; off < 32; off <<= 1) {
        int u = __shfl_up_sync(0xffffffffu, inc, off);
        if (lane >= off) inc += u;
    }
    int wtot = __shfl_sync(0xffffffffu, inc, 31);
    int base = 0;
    if (lane == 31) base = atomicAdd(tot, wtot);
    base = __shfl_sync(0xffffffffu, base, 31);
    if (i < n) {
        int st = base + inc - c;  // exclusive
        start[i] = st;
        cursor[i] = st;
        dinv[i] = rsqrtf(1.0f + (float)c);
    }
}

__global__ void k_build(const int* __restrict__ src, const int* __restrict__ dst,
                        int* cursor, int* perm, int E) {
    int stride = gridDim.x * blockDim.x;
    for (int i = blockIdx.x * blockDim.x + threadIdx.x; i < E; i += stride) {
        int p = atomicAdd(&cursor[dst[i]], 1);
        perm[p] = src[i];
    }
}

// ---------------------------------------------------------------------------
// input loaders (fp32 or fp16 -> half2, optional ReLU)
__device__ __forceinline__ __half2 load_h2(const float* p, bool relu) {
    float2 v = *(const float2*)p;
    if (relu) { v.x = fmaxf(v.x, 0.0f); v.y = fmaxf(v.y, 0.0f); }
    return __floats2half2_rn(v.x, v.y);
}
__device__ __forceinline__ __half2 load_h2(const __half* p, bool relu) {
    __half2 v = *(const __half2*)p;
    if (relu) v = __hmax2(v, __floats2half2_rn(0.0f, 0.0f));
    return v;
}

// ---------------------------------------------------------------------------
// Tensor-core GEMM: hs(half) = (act(x) @ W) * dinv[row]
// mma.sync m16n8k16 f16*f16 -> f32. Block = 256 threads = 8 warps, M-tile 128.
template <int FIN, int FOUT, bool RELU, typename TIN>
__global__ void k_gemm_mma(const TIN* __restrict__ x, const float* __restrict__ W,
                           const float* __restrict__ dinv, __half* __restrict__ h, int N) {
    constexpr int KC = FIN / 16;
    constexpr int NT = FOUT / 8;
    constexpr int ASTR = FIN + 8;
    constexpr int BSTR = FOUT + 8;
    __shared__ __half As[128 * ASTR];
    __shared__ __half Bs[FIN * BSTR];
    int tid = threadIdx.x;
    int base = blockIdx.x * 128;

    for (int i = tid; i < FIN * FOUT; i += 256) {
        int r = i / FOUT, cc = i % FOUT;
        Bs[r * BSTR + cc] = __float2half_rn(W[i]);
    }
    constexpr int PAIRS = 128 * FIN / 2;
    for (int p = tid; p < PAIRS; p += 256) {
        int r = p / (FIN / 2), cp = p % (FIN / 2);
        int grow = base + r;
        __half2 hv = (grow < N) ? load_h2(&x[(long long)grow * FIN + cp * 2], RELU)
                                : __floats2half2_rn(0.0f, 0.0f);
        *(__half2*)&As[r * ASTR + cp * 2] = hv;
    }
    __syncthreads();

    int warp = tid >> 5, lane = tid & 31;
    float acc[NT][4];
#pragma unroll
    for (int nt = 0; nt < NT; nt++)
#pragma unroll
        for (int j = 0; j < 4; j++) acc[nt][j] = 0.0f;

    uint32_t a_addr0 = (uint32_t)__cvta_generic_to_shared(
        &As[(warp * 16 + (lane & 15)) * ASTR + (lane >> 4) * 8]);
    uint32_t b_row = (lane & 15);

#pragma unroll
    for (int kc = 0; kc < KC; kc++) {
        uint32_t a0, a1, a2, a3;
        uint32_t aa = a_addr0 + kc * 16 * 2;
        asm volatile("ldmatrix.sync.aligned.m8n8.x4.shared.b16 {%0,%1,%2,%3}, [%4];"
                     : "=r"(a0), "=r"(a1), "=r"(a2), "=r"(a3) : "r"(aa));
#pragma unroll
        for (int nt = 0; nt < NT; nt++) {
            uint32_t b0, b1;
            uint32_t ba = (uint32_t)__cvta_generic_to_shared(
                &Bs[(kc * 16 + b_row) * BSTR + nt * 8]);
            asm volatile("ldmatrix.sync.aligned.m8n8.x2.trans.shared.b16 {%0,%1}, [%2];"
                         : "=r"(b0), "=r"(b1) : "r"(ba));
            asm volatile(
                "mma.sync.aligned.m16n8k16.row.col.f32.f16.f16.f32 "
                "{%0,%1,%2,%3}, {%4,%5,%6,%7}, {%8,%9}, {%0,%1,%2,%3};"
                : "+f"(acc[nt][0]), "+f"(acc[nt][1]), "+f"(acc[nt][2]), "+f"(acc[nt][3])
                : "r"(a0), "r"(a1), "r"(a2), "r"(a3), "r"(b0), "r"(b1));
        }
    }

    int r0 = base + warp * 16 + (lane >> 2);
    int r1 = r0 + 8;
    float d0 = (r0 < N) ? dinv[r0] : 0.0f;
    float d1 = (r1 < N) ? dinv[r1] : 0.0f;
    int colb = (lane & 3) * 2;
#pragma unroll
    for (int nt = 0; nt < NT; nt++) {
        int col = nt * 8 + colb;
        if (r0 < N)
            *(__half2*)&h[(long long)r0 * FOUT + col] =
                __floats2half2_rn(acc[nt][0] * d0, acc[nt][1] * d0);
        if (r1 < N)
            *(__half2*)&h[(long long)r1 * FOUT + col] =
                __floats2half2_rn(acc[nt][2] * d1, acc[nt][3] * d1);
    }
}

// ---------------------------------------------------------------------------
// CSR aggregation: out[d] = half( dinv[d]*(hs[d] + sum hs[src]) + b )
// F=64: warp per node (32 x half2 lanes = 128B row).
__global__ void k_agg64(const int* __restrict__ start, const int* __restrict__ cnt,
                        const int* __restrict__ perm,
                        const __half* __restrict__ hs, const float* __restrict__ dinv,
                        const float* __restrict__ b, __half* __restrict__ out, int N) {
    int warp = (blockIdx.x * blockDim.x + threadIdx.x) >> 5;
    if (warp >= N) return;
    int lane = threadIdx.x & 31;
    const __half2* H = (const __half2*)hs;
    float2 acc = __half22float2(H[(long long)warp * 32 + lane]);  // self term
    int lo = start[warp], hi = lo + cnt[warp];
    for (int base = lo; base < hi; base += 32) {
        int n = min(32, hi - base);
        int s = (lane < n) ? perm[base + lane] : 0;
        for (int j = 0; j < n; j++) {
            int sj = __shfl_sync(0xffffffffu, s, j);
            float2 v = __half22float2(H[(long long)sj * 32 + lane]);
            acc.x += v.x; acc.y += v.y;
        }
    }
    float d = dinv[warp];
    float2 bb = ((const float2*)b)[lane];
    ((__half2*)out)[(long long)warp * 32 + lane] =
        __floats2half2_rn(acc.x * d + bb.x, acc.y * d + bb.y);
}

// F=32: 16 lanes per node (16 x half2 = 64B row), two nodes per warp.
__global__ void k_agg32(const int* __restrict__ start, const int* __restrict__ cnt,
                        const int* __restrict__ perm,
                        const __half* __restrict__ hs, const float* __restrict__ dinv,
                        const float* __restrict__ b, __half* __restrict__ out, int N) {
    int t = blockIdx.x * blockDim.x + threadIdx.x;
    int node = t >> 4;
    if (node >= N) return;
    int sub = t & 15;
    const __half2* H = (const __half2*)hs;
    float2 acc = __half22float2(H[(long long)node * 16 + sub]);  // self
    int lo = start[node], hi = lo + cnt[node];
    for (int base = lo; base < hi; base += 16) {
        int n = min(16, hi - base);
        int s = (sub < n) ? perm[base + sub] : 0;
        for (int j = 0; j < n; j++) {
            int sj = __shfl_sync(0xffffffffu, s, j, 16);
            float2 v = __half22float2(H[(long long)sj * 16 + sub]);
            acc.x += v.x; acc.y += v.y;
        }
    }
    float d = dinv[node];
    float2 bb = ((const float2*)b)[sub];
    ((__half2*)out)[(long long)node * 16 + sub] =
        __floats2half2_rn(acc.x * d + bb.x, acc.y * d + bb.y);
}

// ---------------------------------------------------------------------------
// Atomic-free pooling over sorted batch; one block per graph, blockDim = F.
template <int F>
__global__ void k_poolg(const __half* __restrict__ x, const int* __restrict__ batch,
                        int N, float* __restrict__ embed, int mxcol, int mncol) {
    int g = blockIdx.x;
    int j = threadIdx.x;
    int lo = 0, hi = N;
    while (lo < hi) { int m = (lo + hi) >> 1; if (batch[m] < g) lo = m + 1; else hi = m; }
    int lo2 = lo, hi2 = N;
    while (lo2 < hi2) { int m = (lo2 + hi2) >> 1; if (batch[m] < g + 1) lo2 = m + 1; else hi2 = m; }
    float mx = 0.0f, sum = 0.0f;
    for (int r = lo; r < lo2; r++) {
        float v = fmaxf(__half2float(x[(long long)r * F + j]), 0.0f);  // ReLU fused
        mx = fmaxf(mx, v);
        sum += v;
    }
    float n = (float)(lo2 - lo);
    embed[(long long)g * 192 + mxcol + j] = mx;
    embed[(long long)g * 192 + mncol + j] = sum / fmaxf(n, 1.0f);
}

// ---------------------------------------------------------------------------
__global__ void k_dense(const float* __restrict__ embed, const float* __restrict__ Wd,
                        const float* __restrict__ bd, const float* __restrict__ Wo,
                        const float* __restrict__ bo, float* __restrict__ out) {
    __shared__ float es[192];
    __shared__ float red[4];
    int g = blockIdx.x, tid = threadIdx.x;
    for (int i = tid; i < 192; i += 128) es[i] = embed[(long long)g * 192 + i];
    __syncthreads();
    float a = bd[tid];
#pragma unroll 8
    for (int k = 0; k < 192; k++) a += es[k] * Wd[k * 128 + tid];
    a = fmaxf(a, 0.0f);
    float v = a * Wo[tid];
#pragma unroll
    for (int o = 16; o > 0; o >>= 1) v += __shfl_down_sync(0xffffffffu, v, o);
    if ((tid & 31) == 0) red[tid >> 5] = v;
    __syncthreads();
    if (tid == 0) out[g] = red[0] + red[1] + red[2] + red[3] + bo[0];
}

// ---------------------------------------------------------------------------
extern "C" void kernel_launch(void* const* d_in, const int* in_sizes, int n_in,
                              void* d_out, int out_size) {
    const float* c       = (const float*)d_in[0];
    const int*   c_edge  = (const int*)d_in[1];
    const int*   c_batch = (const int*)d_in[2];
    const float* s       = (const float*)d_in[3];
    const int*   s_edge  = (const int*)d_in[4];
    const int*   s_batch = (const int*)d_in[5];
    const float* Wc0 = (const float*)d_in[6],  *bc0 = (const float*)d_in[7];
    const float* Wc1 = (const float*)d_in[8],  *bc1 = (const float*)d_in[9];
    const float* Wc2 = (const float*)d_in[10], *bc2 = (const float*)d_in[11];
    const float* Ws0 = (const float*)d_in[12], *bs0 = (const float*)d_in[13];
    const float* Ws1 = (const float*)d_in[14], *bs1 = (const float*)d_in[15];
    const float* Ws2 = (const float*)d_in[16], *bs2 = (const float*)d_in[17];
    const float* Wd  = (const float*)d_in[18], *bd  = (const float*)d_in[19];
    const float* Wo  = (const float*)d_in[20], *bo  = (const float*)d_in[21];

    int Nc = in_sizes[0] / 64;
    int Ec = in_sizes[1] / 2;
    int Ns = in_sizes[3] / 64;
    int Es = in_sizes[4] / 2;

    float* out   = (float*)d_out;
    float* embed = out + NG;  // [NG, 192]

    __half *hs_c, *hB_c, *hs_s, *hB_s;
    float *dinv_c, *dinv_s;
    int *cnt_c, *cnt_s, *start_c, *start_s, *cursor_c, *cursor_s;
    int *perm_c, *perm_s, *tot_c, *tot_s;
    cudaGetSymbolAddress((void**)&hs_c, g_hs_c);
    cudaGetSymbolAddress((void**)&hB_c, g_hB_c);
    cudaGetSymbolAddress((void**)&hs_s, g_hs_s);
    cudaGetSymbolAddress((void**)&hB_s, g_hB_s);
    cudaGetSymbolAddress((void**)&dinv_c, g_dinv_c);
    cudaGetSymbolAddress((void**)&dinv_s, g_dinv_s);
    cudaGetSymbolAddress((void**)&cnt_c, g_cnt_c);
    cudaGetSymbolAddress((void**)&cnt_s, g_cnt_s);
    cudaGetSymbolAddress((void**)&start_c, g_start_c);
    cudaGetSymbolAddress((void**)&start_s, g_start_s);
    cudaGetSymbolAddress((void**)&cursor_c, g_cursor_c);
    cudaGetSymbolAddress((void**)&cursor_s, g_cursor_s);
    cudaGetSymbolAddress((void**)&perm_c, g_perm_c);
    cudaGetSymbolAddress((void**)&perm_s, g_perm_s);
    cudaGetSymbolAddress((void**)&tot_c, g_tot_c);
    cudaGetSymbolAddress((void**)&tot_s, g_tot_s);

    // Streams: st0 = c-chain, s2 = s-chain, s3 = c-gemm0, s4 = s-gemm0
    static cudaStream_t s2 = nullptr, s3 = nullptr, s4 = nullptr;
    static cudaEvent_t evF = nullptr, evA = nullptr, evB = nullptr, evJ = nullptr;
    static bool tried = false;
    if (!tried) {
        tried = true;
        bool ok = cudaStreamCreateWithFlags(&s2, cudaStreamNonBlocking) == cudaSuccess &&
                  cudaStreamCreateWithFlags(&s3, cudaStreamNonBlocking) == cudaSuccess &&
                  cudaStreamCreateWithFlags(&s4, cudaStreamNonBlocking) == cudaSuccess;
        if (ok) {
            cudaEventCreateWithFlags(&evF, cudaEventDisableTiming);
            cudaEventCreateWithFlags(&evA, cudaEventDisableTiming);
            cudaEventCreateWithFlags(&evB, cudaEventDisableTiming);
            cudaEventCreateWithFlags(&evJ, cudaEventDisableTiming);
        } else {
            s2 = s3 = s4 = nullptr;
        }
    }
    bool fork = (s2 != nullptr);
    cudaStream_t st0 = 0;
    cudaStream_t stS = fork ? s2 : st0;
    cudaStream_t stA = fork ? s3 : st0;
    cudaStream_t stB = fork ? s4 : st0;

    if (fork) {
        cudaEventRecord(evF, st0);
        cudaStreamWaitEvent(stS, evF, 0);
        cudaStreamWaitEvent(stA, evF, 0);
        cudaStreamWaitEvent(stB, evF, 0);
    }

    const int T = 256;
    const int GS = 1184;

    // ================= c branch (F=64) =================
    {
        int N = Nc, E = Ec;
        // CSR chain on st0
        k_zero<<<(N + T - 1) / T, T, 0, st0>>>(cnt_c, tot_c, N);
        k_count<<<GS, T, 0, st0>>>(c_edge + E, E, cnt_c);
        k_offsets<<<(N + T - 1) / T, T, 0, st0>>>(cnt_c, start_c, cursor_c, dinv_c, tot_c, N);
        k_build<<<GS, T, 0, st0>>>(c_edge, c_edge + E, cursor_c, perm_c, E);
        // NOTE: gemm0 needs dinv (from k_offsets). Run gemm0 on stA after the
        // offsets kernel; overlap with k_build.
        if (fork) {
            cudaEventRecord(evA, st0);  // after k_build enqueue order — need dinv only;
        }
        // gemm0 depends on dinv: enqueue on stA waiting for offsets. Since we
        // recorded evA after k_build, gemm0 would serialize; instead record a
        // dedicated event right after k_offsets by re-ordering: (handled below
        // for simplicity: run gemm0 on st0's chain via stA waiting on evA).
        int mmaB = (N + 127) / 128;
        int aggB = (N * 32 + T - 1) / T;
        if (fork) {
            cudaStreamWaitEvent(stA, evA, 0);
            k_gemm_mma<64, 64, false><<<mmaB, 256, 0, stA>>>(c, Wc0, dinv_c, hs_c, N);
            cudaEventRecord(evA, stA);
            cudaStreamWaitEvent(st0, evA, 0);
        } else {
            k_gemm_mma<64, 64, false><<<mmaB, 256, 0, st0>>>(c, Wc0, dinv_c, hs_c, N);
        }
        k_agg64<<<aggB, T, 0, st0>>>(start_c, cnt_c, perm_c, hs_c, dinv_c, bc0, hB_c, N);
        k_gemm_mma<64, 64, true><<<mmaB, 256, 0, st0>>>(hB_c, Wc1, dinv_c, hs_c, N);
        k_agg64<<<aggB, T, 0, st0>>>(start_c, cnt_c, perm_c, hs_c, dinv_c, bc1, hB_c, N);
        k_gemm_mma<64, 64, true><<<mmaB, 256, 0, st0>>>(hB_c, Wc2, dinv_c, hs_c, N);
        k_agg64<<<aggB, T, 0, st0>>>(start_c, cnt_c, perm_c, hs_c, dinv_c, bc2, hB_c, N);
        k_poolg<64><<<NG, 64, 0, st0>>>(hB_c, c_batch, N, embed, 0, 64);
    }

    // ================= s branch (F=32) =================
    {
        int N = Ns, E = Es;
        k_zero<<<(N + T - 1) / T, T, 0, stS>>>(cnt_s, tot_s, N);
        k_count<<<GS, T, 0, stS>>>(s_edge + E, E, cnt_s);
        k_offsets<<<(N + T - 1) / T, T, 0, stS>>>(cnt_s, start_s, cursor_s, dinv_s, tot_s, N);
        k_build<<<GS, T, 0, stS>>>(s_edge, s_edge + E, cursor_s, perm_s, E);
        int mmaB = (N + 127) / 128;
        int aggB = (N * 16 + T - 1) / T;
        if (fork) {
            cudaEventRecord(evB, stS);
            cudaStreamWaitEvent(stB, evB, 0);
            k_gemm_mma<64, 32, false><<<mmaB, 256, 0, stB>>>(s, Ws0, dinv_s, hs_s, N);
            cudaEventRecord(evB, stB);
            cudaStreamWaitEvent(stS, evB, 0);
        } else {
            k_gemm_mma<64, 32, false><<<mmaB, 256, 0, stS>>>(s, Ws0, dinv_s, hs_s, N);
        }
        k_agg32<<<aggB, T, 0, stS>>>(start_s, cnt_s, perm_s, hs_s, dinv_s, bs0, hB_s, N);
        k_gemm_mma<32, 32, true><<<mmaB, 256, 0, stS>>>(hB_s, Ws1, dinv_s, hs_s, N);
        k_agg32<<<aggB, T, 0, stS>>>(start_s, cnt_s, perm_s, hs_s, dinv_s, bs1, hB_s, N);
        k_gemm_mma<32, 32, true><<<mmaB, 256, 0, stS>>>(hB_s, Ws2, dinv_s, hs_s, N);
        k_agg32<<<aggB, T, 0, stS>>>(start_s, cnt_s, perm_s, hs_s, dinv_s, bs2, hB_s, N);
        k_poolg<32><<<NG, 32, 0, stS>>>(hB_s, s_batch, N, embed, 128, 160);
    }

    if (fork) {
        cudaEventRecord(evJ, stS);
        cudaStreamWaitEvent(st0, evJ, 0);
    }

    // ================= head =================
    k_dense<<<NG, 128, 0, st0>>>(embed, Wd, bd, Wo, bo, out);
}